// round 10
// baseline (speedup 1.0000x reference)
#include <cuda_runtime.h>
#include <math.h>

// ---------------------------------------------------------------------------
// MLGKA layer. R5: big GEMMs on tensor cores via mma.sync m16n8k8 tf32 with
// 3xTF32 error compensation (hi/lo split) -> fp32-grade accuracy at tensor
// speed. Attention plumbing / LN / swiglu unchanged from the passing R4.
// ---------------------------------------------------------------------------

constexpr int B_    = 4;
constexpr int S_    = 4096;
constexpr int T_    = B_ * S_;        // 16384 tokens
constexpr int D_    = 2048;
constexpr int DFF_  = 8192;
constexpr int H_    = 16;
constexpr int HKV_  = 8;
constexpr int DH_   = 128;
constexpr int RQ_   = 64;
constexpr int RKV_  = 64;
constexpr int KD_   = 64;
constexpr int F_    = 128;            // 2*KD
constexpr int NSPLIT = 8;
constexpr int CHUNK  = S_ / NSPLIT;   // 512

// ------------------------------ scratch (static device globals) -----------
__device__ float g_cq     [(size_t)T_ * RQ_];
__device__ float g_ckv    [(size_t)T_ * RKV_];
__device__ float g_q      [(size_t)T_ * (H_  * DH_)];
__device__ float g_k      [(size_t)T_ * (HKV_* DH_)];
__device__ float g_v      [(size_t)T_ * (HKV_* DH_)];
__device__ float g_phiq   [(size_t)B_ * H_   * S_ * F_];
__device__ float g_phik   [(size_t)B_ * HKV_ * S_ * F_];
__device__ float g_kvpart [(size_t)B_ * HKV_ * NSPLIT * F_ * DH_];
__device__ float g_kvx    [(size_t)B_ * H_   * F_ * DH_];
__device__ float g_z      [(size_t)B_ * HKV_ * F_];
__device__ float g_den    [(size_t)B_ * H_   * S_];
__device__ float g_num    [(size_t)B_ * H_   * S_ * DH_];
__device__ float g_attn   [(size_t)T_ * D_];
__device__ float g_attnout[(size_t)T_ * D_];
__device__ float g_hbuf   [(size_t)T_ * D_];
__device__ float g_gate   [(size_t)T_ * DFF_];
__device__ float g_up     [(size_t)T_ * DFF_];
__device__ float g_ffn    [(size_t)T_ * D_];

// =========================== tensor-core GEMM (3xTF32) =====================
// C[M,N] = A[M,K] @ B[K,N], row-major, fp32 in/out, fp32-grade accuracy via
// hi/lo tf32 split. Requirements: M%128==0, N%128==0, K%8==0,
// C 8B-aligned rows (ldc even). Batched via blockIdx.z strides.

__device__ __forceinline__ float f2tf32(float x) {
    unsigned u;
    asm("cvt.rna.tf32.f32 %0, %1;" : "=r"(u) : "f"(x));
    return __uint_as_float(u);
}

__device__ __forceinline__ void mma8(float4& d, const float* a, const float* b) {
    asm("mma.sync.aligned.m16n8k8.row.col.f32.tf32.tf32.f32 "
        "{%0,%1,%2,%3}, {%4,%5,%6,%7}, {%8,%9}, {%0,%1,%2,%3};"
        : "+f"(d.x), "+f"(d.y), "+f"(d.z), "+f"(d.w)
        : "r"(__float_as_uint(a[0])), "r"(__float_as_uint(a[1])),
          "r"(__float_as_uint(a[2])), "r"(__float_as_uint(a[3])),
          "r"(__float_as_uint(b[0])), "r"(__float_as_uint(b[1])));
}

// smem tile: [k(8)][m or n (128) + pad 8] -> pitch 136 floats.
// Fragment LDS bank = (136*k + idx) % 32 = (8*k + idx%32): tig in 0..3,
// g in 0..7 -> 8*tig+g unique in 0..31 => conflict-free.
__device__ __forceinline__ void compute_step(
    const float (*sAh)[136], const float (*sAl)[136],
    const float (*sBh)[136], const float (*sBl)[136],
    int m0, int n0, int g, int tig, float4 acc[4][4])
{
    float ah[4][4], al[4][4];
#pragma unroll
    for (int im = 0; im < 4; im++) {
        const int r = m0 + im * 16 + g;
        ah[im][0] = sAh[tig    ][r];     ah[im][1] = sAh[tig    ][r + 8];
        ah[im][2] = sAh[tig + 4][r];     ah[im][3] = sAh[tig + 4][r + 8];
        al[im][0] = sAl[tig    ][r];     al[im][1] = sAl[tig    ][r + 8];
        al[im][2] = sAl[tig + 4][r];     al[im][3] = sAl[tig + 4][r + 8];
    }
    float bh[4][2], bl[4][2];
#pragma unroll
    for (int in_ = 0; in_ < 4; in_++) {
        const int nb = n0 + in_ * 8 + g;
        bh[in_][0] = sBh[tig][nb];       bh[in_][1] = sBh[tig + 4][nb];
        bl[in_][0] = sBl[tig][nb];       bl[in_][1] = sBl[tig + 4][nb];
    }
#pragma unroll
    for (int im = 0; im < 4; im++)
#pragma unroll
        for (int in_ = 0; in_ < 4; in_++) {
            mma8(acc[im][in_], ah[im], bh[in_]);   // hi*hi
            mma8(acc[im][in_], ah[im], bl[in_]);   // hi*lo
            mma8(acc[im][in_], al[im], bh[in_]);   // lo*hi
        }
}

__global__ __launch_bounds__(256)
void tgemm3x(const float* __restrict__ A, const float* __restrict__ Bm,
             float* __restrict__ C, int M, int N, int K,
             int lda, int ldb, int ldc,
             long long sA, long long sB, long long sC)
{
    A  += (long long)blockIdx.z * sA;
    Bm += (long long)blockIdx.z * sB;
    C  += (long long)blockIdx.z * sC;

    __shared__ __align__(16) float sAh[2][8][136], sAl[2][8][136];
    __shared__ __align__(16) float sBh[2][8][136], sBl[2][8][136];

    const int tid  = threadIdx.x;
    const int w    = tid >> 5;
    const int lane = tid & 31;
    const int g    = lane >> 2;
    const int tig  = lane & 3;
    const int m0   = (w & 1) * 64;      // warp grid 2 (M) x 4 (N)
    const int n0   = (w >> 1) * 32;
    const int rowBase = blockIdx.y * 128;
    const int colBase = blockIdx.x * 128;

    // loaders: A tile 128x8 (one float4/thread along k), B tile 8x128
    const int aRow = tid >> 1, aK = (tid & 1) << 2;
    const int bK   = tid >> 5, bN = (tid & 31) << 2;
    const float* Ap = A + (size_t)(rowBase + aRow) * lda + aK;
    const float* Bp = Bm + (size_t)bK * ldb + colBase + bN;

    float4 acc[4][4];
#pragma unroll
    for (int i = 0; i < 4; i++)
#pragma unroll
        for (int j = 0; j < 4; j++) acc[i][j] = make_float4(0.f, 0.f, 0.f, 0.f);

    // ---- fill buffer 0 ----
    float4 a4 = *reinterpret_cast<const float4*>(Ap);
    float4 b4 = *reinterpret_cast<const float4*>(Bp);
    {
        float av[4] = {a4.x, a4.y, a4.z, a4.w};
#pragma unroll
        for (int j = 0; j < 4; j++) {
            float hi = f2tf32(av[j]);
            sAh[0][aK + j][aRow] = hi;
            sAl[0][aK + j][aRow] = f2tf32(av[j] - hi);
        }
        float4 bhv, blv;
        bhv.x = f2tf32(b4.x); blv.x = f2tf32(b4.x - bhv.x);
        bhv.y = f2tf32(b4.y); blv.y = f2tf32(b4.y - bhv.y);
        bhv.z = f2tf32(b4.z); blv.z = f2tf32(b4.z - bhv.z);
        bhv.w = f2tf32(b4.w); blv.w = f2tf32(b4.w - bhv.w);
        *reinterpret_cast<float4*>(&sBh[0][bK][bN]) = bhv;
        *reinterpret_cast<float4*>(&sBl[0][bK][bN]) = blv;
    }
    __syncthreads();

    int buf = 0;
    for (int k0 = 8; k0 < K; k0 += 8) {
        // prefetch next tile
        a4 = *reinterpret_cast<const float4*>(Ap + k0);
        b4 = *reinterpret_cast<const float4*>(Bp + (size_t)k0 * ldb);

        compute_step(sAh[buf], sAl[buf], sBh[buf], sBl[buf], m0, n0, g, tig, acc);

        const int nb = buf ^ 1;
        float av[4] = {a4.x, a4.y, a4.z, a4.w};
#pragma unroll
        for (int j = 0; j < 4; j++) {
            float hi = f2tf32(av[j]);
            sAh[nb][aK + j][aRow] = hi;
            sAl[nb][aK + j][aRow] = f2tf32(av[j] - hi);
        }
        float4 bhv, blv;
        bhv.x = f2tf32(b4.x); blv.x = f2tf32(b4.x - bhv.x);
        bhv.y = f2tf32(b4.y); blv.y = f2tf32(b4.y - bhv.y);
        bhv.z = f2tf32(b4.z); blv.z = f2tf32(b4.z - bhv.z);
        bhv.w = f2tf32(b4.w); blv.w = f2tf32(b4.w - bhv.w);
        *reinterpret_cast<float4*>(&sBh[nb][bK][bN]) = bhv;
        *reinterpret_cast<float4*>(&sBl[nb][bK][bN]) = blv;
        __syncthreads();
        buf = nb;
    }
    compute_step(sAh[buf], sAl[buf], sBh[buf], sBl[buf], m0, n0, g, tig, acc);

    // ---- epilogue (no guards: M,N multiples of 128) ----
#pragma unroll
    for (int im = 0; im < 4; im++) {
        const int r = rowBase + m0 + im * 16 + g;
#pragma unroll
        for (int in_ = 0; in_ < 4; in_++) {
            const int cc = colBase + n0 + in_ * 8 + 2 * tig;
            float2 v0 = make_float2(acc[im][in_].x, acc[im][in_].y);
            float2 v1 = make_float2(acc[im][in_].z, acc[im][in_].w);
            *reinterpret_cast<float2*>(C + (size_t)r * ldc + cc)       = v0;
            *reinterpret_cast<float2*>(C + (size_t)(r + 8) * ldc + cc) = v1;
        }
    }
}

// ------------------------------ fp32 SGEMM (small N / ragged shapes) ------
__global__ __launch_bounds__(256, 2)
void sgemm_nn(const float* __restrict__ A, const float* __restrict__ Bm,
              float* __restrict__ C,
              int M, int N, int K, int lda, int ldb, int ldc,
              long long sA, long long sB, long long sC)
{
    A  += (long long)blockIdx.z * sA;
    Bm += (long long)blockIdx.z * sB;
    C  += (long long)blockIdx.z * sC;

    __shared__ float As[8][132];
    __shared__ float Bs[8][128];

    const int tid = threadIdx.x;
    const int tx  = tid & 15;
    const int ty  = tid >> 4;
    const int rowBase = blockIdx.y * 128;
    const int colBase = blockIdx.x * 128;

    const int aRow = tid >> 1;
    const int aCol = (tid & 1) << 2;
    const int bRow = tid >> 5;
    const int bCol = (tid & 31) << 2;

    float acc[8][8];
#pragma unroll
    for (int i = 0; i < 8; i++)
#pragma unroll
        for (int j = 0; j < 8; j++) acc[i][j] = 0.f;

    const int  gArow = rowBase + aRow;
    const bool aInM  = (gArow < M);
    const float* Aptr = A + (size_t)(aInM ? gArow : 0) * lda + aCol;
    const int  gBcol = colBase + bCol;

    for (int k0 = 0; k0 < K; k0 += 8) {
        float4 a4 = make_float4(0.f, 0.f, 0.f, 0.f);
        if (aInM) a4 = *reinterpret_cast<const float4*>(Aptr + k0);
        As[aCol + 0][aRow] = a4.x;
        As[aCol + 1][aRow] = a4.y;
        As[aCol + 2][aRow] = a4.z;
        As[aCol + 3][aRow] = a4.w;

        float4 b4;
        const float* bp = Bm + (size_t)(k0 + bRow) * ldb;
        if (gBcol + 3 < N) {
            b4 = *reinterpret_cast<const float4*>(bp + gBcol);
        } else {
            b4.x = (gBcol + 0 < N) ? bp[gBcol + 0] : 0.f;
            b4.y = (gBcol + 1 < N) ? bp[gBcol + 1] : 0.f;
            b4.z = (gBcol + 2 < N) ? bp[gBcol + 2] : 0.f;
            b4.w = (gBcol + 3 < N) ? bp[gBcol + 3] : 0.f;
        }
        *reinterpret_cast<float4*>(&Bs[bRow][bCol]) = b4;
        __syncthreads();

#pragma unroll
        for (int kk = 0; kk < 8; kk++) {
            float aR[8], bR[8];
#pragma unroll
            for (int i = 0; i < 8; i++) aR[i] = As[kk][ty + 16 * i];
#pragma unroll
            for (int j = 0; j < 8; j++) bR[j] = Bs[kk][tx + 16 * j];
#pragma unroll
            for (int i = 0; i < 8; i++)
#pragma unroll
                for (int j = 0; j < 8; j++) acc[i][j] += aR[i] * bR[j];
        }
        __syncthreads();
    }

#pragma unroll
    for (int i = 0; i < 8; i++) {
        int r = rowBase + ty + 16 * i;
        if (r >= M) continue;
        float* crow = C + (size_t)r * ldc;
#pragma unroll
        for (int j = 0; j < 8; j++) {
            int c = colBase + tx + 16 * j;
            if (c < N) crow[c] = acc[i][j];
        }
    }
}

// ------------------------------ phi (random Fourier features) -------------
__global__ void phi_kernel(const float* __restrict__ qk,
                           const float* __restrict__ omega,
                           float* __restrict__ phi,
                           int nheads, int ldq)
{
    const long long bid = blockIdx.x;             // ((b*nh + h)*S + s)
    const int s = (int)(bid % S_);
    const int h = (int)((bid / S_) % nheads);
    const int b = (int)(bid / ((long long)S_ * nheads));
    const long long t = (long long)b * S_ + s;

    __shared__ float qs[DH_];
    const int k = threadIdx.x;                    // 0..63
    const float* row = qk + (size_t)t * ldq + (size_t)h * DH_;
    qs[k]      = row[k];
    qs[k + 64] = row[k + 64];
    __syncthreads();

    float proj = 0.f;
#pragma unroll 8
    for (int d = 0; d < DH_; d++) proj += qs[d] * omega[d * KD_ + k];

    float sv, cv;
    sincosf(proj, &sv, &cv);
    float* prow = phi + bid * (long long)F_;
    prow[k]      = cv * 0.125f;     // 1/sqrt(64)
    prow[k + 64] = sv * 0.125f;
}

// ------------------------------ z = sum_s phi_k ---------------------------
__global__ void z_kernel(const float* __restrict__ phik, float* __restrict__ z)
{
    const int bh = blockIdx.x;
    const int f  = threadIdx.x;
    const float* p = phik + (size_t)bh * S_ * F_ + f;
    float sum = 0.f;
#pragma unroll 8
    for (int i = 0; i < S_; i++) sum += p[(size_t)i * F_];
    z[bh * F_ + f] = sum;
}

// ------------------------------ kv partial --------------------------------
__global__ __launch_bounds__(256, 2)
void kv_partial(const float* __restrict__ phik, const float* __restrict__ v,
                float* __restrict__ part)
{
    const int bid   = blockIdx.x;
    const int split = bid % NSPLIT;
    const int bh    = bid / NSPLIT;
    const int b     = bh / HKV_;
    const int hk    = bh % HKV_;

    const float* A  = phik + (size_t)bh * S_ * F_ + (size_t)split * CHUNK * F_;
    const float* Bm = v + ((size_t)b * S_ + (size_t)split * CHUNK) * (HKV_ * DH_)
                        + (size_t)hk * DH_;
    float* C = part + (size_t)bid * F_ * DH_;

    __shared__ float As[8][128];
    __shared__ float Bs[8][128];
    const int tid = threadIdx.x;
    const int tx  = tid & 15;
    const int ty  = tid >> 4;
    const int lRow = tid >> 5;
    const int lCol = (tid & 31) << 2;

    float acc[8][8];
#pragma unroll
    for (int i = 0; i < 8; i++)
#pragma unroll
        for (int j = 0; j < 8; j++) acc[i][j] = 0.f;

    for (int k0 = 0; k0 < CHUNK; k0 += 8) {
        *reinterpret_cast<float4*>(&As[lRow][lCol]) =
            *reinterpret_cast<const float4*>(A + (size_t)(k0 + lRow) * F_ + lCol);
        *reinterpret_cast<float4*>(&Bs[lRow][lCol]) =
            *reinterpret_cast<const float4*>(Bm + (size_t)(k0 + lRow) * (HKV_ * DH_) + lCol);
        __syncthreads();
#pragma unroll
        for (int kk = 0; kk < 8; kk++) {
            float aR[8], bR[8];
#pragma unroll
            for (int i = 0; i < 8; i++) aR[i] = As[kk][ty + 16 * i];
#pragma unroll
            for (int j = 0; j < 8; j++) bR[j] = Bs[kk][tx + 16 * j];
#pragma unroll
            for (int i = 0; i < 8; i++)
#pragma unroll
                for (int j = 0; j < 8; j++) acc[i][j] += aR[i] * bR[j];
        }
        __syncthreads();
    }
#pragma unroll
    for (int i = 0; i < 8; i++)
#pragma unroll
        for (int j = 0; j < 8; j++)
            C[(size_t)(ty + 16 * i) * DH_ + (tx + 16 * j)] = acc[i][j];
}

// ------------------------------ reduce splits + GQA expand ----------------
__global__ void kv_reduce_expand(const float* __restrict__ part,
                                 float* __restrict__ kvx)
{
    const long long n = (long long)B_ * H_ * F_ * DH_;
    long long i = (long long)blockIdx.x * blockDim.x + threadIdx.x;
    if (i >= n) return;
    const int fd = (int)(i & (F_ * DH_ - 1));
    const int h  = (int)((i >> 14) & (H_ - 1));
    const int b  = (int)(i >> 18);
    const int bh = b * HKV_ + (h >> 1);
    float s = 0.f;
#pragma unroll
    for (int sp = 0; sp < NSPLIT; sp++)
        s += part[(((size_t)bh * NSPLIT + sp) << 14) + fd];
    kvx[i] = s;
}

// ------------------------------ den ---------------------------------------
__global__ void den_kernel(const float* __restrict__ phiq,
                           const float* __restrict__ z,
                           float* __restrict__ den)
{
    const long long warp = ((long long)blockIdx.x * blockDim.x + threadIdx.x) >> 5;
    const int lane = threadIdx.x & 31;
    if (warp >= (long long)B_ * H_ * S_) return;
    const int h = (int)((warp / S_) % H_);
    const int b = (int)(warp / ((long long)S_ * H_));
    const float* zp = z + (size_t)(b * HKV_ + (h >> 1)) * F_;
    const float* pr = phiq + warp * (long long)F_;
    float sum = 0.f;
#pragma unroll
    for (int j = 0; j < 4; j++) {
        int f = lane + 32 * j;
        sum += pr[f] * zp[f];
    }
#pragma unroll
    for (int o = 16; o; o >>= 1) sum += __shfl_xor_sync(0xffffffffu, sum, o);
    if (lane == 0) den[warp] = sum;
}

// ------------------------------ attn assembly -----------------------------
__global__ void attn_assemble(const float* __restrict__ num,
                              const float* __restrict__ den,
                              float* __restrict__ attn)
{
    const long long n = (long long)B_ * H_ * S_ * DH_;
    long long i = (long long)blockIdx.x * blockDim.x + threadIdx.x;
    if (i >= n) return;
    const int d = (int)(i & (DH_ - 1));
    const long long r = i >> 7;
    const int s = (int)(r & (S_ - 1));
    const int h = (int)((r >> 12) & (H_ - 1));
    const int b = (int)(r >> 16);
    const float val = num[i] / (den[r] + 1e-6f);
    attn[((size_t)b * S_ + s) * (size_t)D_ + (size_t)h * DH_ + d] = val;
}

// ------------------------------ out = LN(a+b)*g + beta --------------------
__global__ __launch_bounds__(256)
void add_ln_kernel(const float* __restrict__ a, const float* __restrict__ bb,
                   const float* __restrict__ g, const float* __restrict__ beta,
                   float* __restrict__ out)
{
    __shared__ float sh[10];
    const size_t row = blockIdx.x;
    const float* ar = a  + row * D_;
    const float* br = bb + row * D_;
    const int tid = threadIdx.x;

    float loc[8];
    float sum = 0.f;
#pragma unroll
    for (int j = 0; j < 8; j++) {
        int c = tid + 256 * j;
        float v = ar[c] + br[c];
        loc[j] = v;
        sum += v;
    }
#pragma unroll
    for (int o = 16; o; o >>= 1) sum += __shfl_xor_sync(0xffffffffu, sum, o);
    if ((tid & 31) == 0) sh[tid >> 5] = sum;
    __syncthreads();
    if (tid == 0) {
        float s = 0.f;
        for (int i = 0; i < 8; i++) s += sh[i];
        sh[8] = s;
    }
    __syncthreads();
    const float mu = sh[8] * (1.f / D_);

    float sq = 0.f;
#pragma unroll
    for (int j = 0; j < 8; j++) {
        float dv = loc[j] - mu;
        sq += dv * dv;
    }
    __syncthreads();
#pragma unroll
    for (int o = 16; o; o >>= 1) sq += __shfl_xor_sync(0xffffffffu, sq, o);
    if ((tid & 31) == 0) sh[tid >> 5] = sq;
    __syncthreads();
    if (tid == 0) {
        float s = 0.f;
        for (int i = 0; i < 8; i++) s += sh[i];
        sh[9] = s;
    }
    __syncthreads();
    const float rstd = rsqrtf(sh[9] * (1.f / D_) + 1e-5f);

    float* orow = out + row * D_;
#pragma unroll
    for (int j = 0; j < 8; j++) {
        int c = tid + 256 * j;
        orow[c] = (loc[j] - mu) * rstd * g[c] + beta[c];
    }
}

// ------------------------------ gate *= silu(up) --------------------------
__global__ void swiglu_kernel(float* __restrict__ gate,
                              const float* __restrict__ up)
{
    const long long n = (long long)T_ * DFF_;
    long long i = (long long)blockIdx.x * blockDim.x + threadIdx.x;
    if (i >= n) return;
    const float u = up[i];
    const float s = u / (1.f + expf(-u));
    gate[i] = gate[i] * s;
}

// ---------------------------------------------------------------------------
extern "C" void kernel_launch(void* const* d_in, const int* in_sizes, int n_in,
                              void* d_out, int out_size)
{
    const float* x      = (const float*)d_in[0];
    const float* W_dq   = (const float*)d_in[1];
    const float* W_uq   = (const float*)d_in[2];
    const float* W_dkv  = (const float*)d_in[3];
    const float* W_uk   = (const float*)d_in[4];
    const float* W_uv   = (const float*)d_in[5];
    const float* omega  = (const float*)d_in[6];
    const float* W_o    = (const float*)d_in[7];
    const float* ln1_g  = (const float*)d_in[8];
    const float* ln1_b  = (const float*)d_in[9];
    const float* gate_W = (const float*)d_in[10];
    const float* up_W   = (const float*)d_in[11];
    const float* down_W = (const float*)d_in[12];
    const float* ln2_g  = (const float*)d_in[13];
    const float* ln2_b  = (const float*)d_in[14];
    float* out = (float*)d_out;

    float *cq, *ckv, *q, *k, *v, *phiq, *phik, *kvpart, *kvx, *z, *den, *num;
    float *attn, *attnout, *hbuf, *gate, *up, *ffn;
    cudaGetSymbolAddress((void**)&cq,      g_cq);
    cudaGetSymbolAddress((void**)&ckv,     g_ckv);
    cudaGetSymbolAddress((void**)&q,       g_q);
    cudaGetSymbolAddress((void**)&k,       g_k);
    cudaGetSymbolAddress((void**)&v,       g_v);
    cudaGetSymbolAddress((void**)&phiq,    g_phiq);
    cudaGetSymbolAddress((void**)&phik,    g_phik);
    cudaGetSymbolAddress((void**)&kvpart,  g_kvpart);
    cudaGetSymbolAddress((void**)&kvx,     g_kvx);
    cudaGetSymbolAddress((void**)&z,       g_z);
    cudaGetSymbolAddress((void**)&den,     g_den);
    cudaGetSymbolAddress((void**)&num,     g_num);
    cudaGetSymbolAddress((void**)&attn,    g_attn);
    cudaGetSymbolAddress((void**)&attnout, g_attnout);
    cudaGetSymbolAddress((void**)&hbuf,    g_hbuf);
    cudaGetSymbolAddress((void**)&gate,    g_gate);
    cudaGetSymbolAddress((void**)&up,      g_up);
    cudaGetSymbolAddress((void**)&ffn,     g_ffn);

    // --- low-rank down-projections (N=64 -> keep fp32 sgemm) ---
    sgemm_nn<<<dim3(1, 128, 1), 256>>>(x,  W_dq,  cq,  T_, RQ_,  D_, D_, RQ_,  RQ_, 0, 0, 0);
    sgemm_nn<<<dim3(1, 128, 1), 256>>>(x,  W_dkv, ckv, T_, RKV_, D_, D_, RKV_, RKV_, 0, 0, 0);

    // --- up-projections on tensor cores (K=64) ---
    tgemm3x<<<dim3(16, 128, 1), 256>>>(cq,  W_uq, q, T_, H_ * DH_,  RQ_,
                                       RQ_,  H_ * DH_,  H_ * DH_, 0, 0, 0);
    tgemm3x<<<dim3(8, 128, 1), 256>>>(ckv, W_uk, k, T_, HKV_ * DH_, RKV_,
                                      RKV_, HKV_ * DH_, HKV_ * DH_, 0, 0, 0);
    tgemm3x<<<dim3(8, 128, 1), 256>>>(ckv, W_uv, v, T_, HKV_ * DH_, RKV_,
                                      RKV_, HKV_ * DH_, HKV_ * DH_, 0, 0, 0);

    // --- random Fourier features ---
    phi_kernel<<<B_ * H_   * S_, 64>>>(q, omega, phiq, H_,   H_   * DH_);
    phi_kernel<<<B_ * HKV_ * S_, 64>>>(k, omega, phik, HKV_, HKV_ * DH_);

    // --- linear attention state ---
    z_kernel<<<B_ * HKV_, 128>>>(phik, z);
    kv_partial<<<B_ * HKV_ * NSPLIT, 256>>>(phik, v, kvpart);
    kv_reduce_expand<<<(B_ * H_ * F_ * DH_ + 255) / 256, 256>>>(kvpart, kvx);
    den_kernel<<<(B_ * H_ * S_) / 8, 256>>>(phiq, z, den);

    // num = phi_q @ kv (batched over B*H) on tensor cores
    tgemm3x<<<dim3(1, 32, B_ * H_), 256>>>(phiq, kvx, num,
                                           S_, DH_, F_, F_, DH_, DH_,
                                           (long long)S_ * F_,
                                           (long long)F_ * DH_,
                                           (long long)S_ * DH_);
    attn_assemble<<<(B_ * H_ * S_ * DH_ + 255) / 256, 256>>>(num, den, attn);

    // --- output projection + residual/LN ---
    tgemm3x<<<dim3(16, 128, 1), 256>>>(attn, W_o, attnout, T_, D_, D_,
                                       D_, D_, D_, 0, 0, 0);
    add_ln_kernel<<<T_, 256>>>(x, attnout, ln1_g, ln1_b, hbuf);

    // --- SwiGLU FFN on tensor cores ---
    tgemm3x<<<dim3(64, 128, 1), 256>>>(hbuf, gate_W, gate, T_, DFF_, D_,
                                       D_, DFF_, DFF_, 0, 0, 0);
    tgemm3x<<<dim3(64, 128, 1), 256>>>(hbuf, up_W,   up,   T_, DFF_, D_,
                                       D_, DFF_, DFF_, 0, 0, 0);
    swiglu_kernel<<<(int)(((long long)T_ * DFF_ + 255) / 256), 256>>>(gate, up);
    tgemm3x<<<dim3(16, 128, 1), 256>>>(gate, down_W, ffn, T_, D_, DFF_,
                                       DFF_, D_, D_, 0, 0, 0);

    // --- final residual/LN -> output ---
    add_ln_kernel<<<T_, 256>>>(hbuf, ffn, ln2_g, ln2_b, out);
}

// round 11
// speedup vs baseline: 1.0000x; 1.0000x over previous
#include <cuda_runtime.h>
#include <math.h>

// ---------------------------------------------------------------------------
// MLGKA layer. R5: big GEMMs on tensor cores via mma.sync m16n8k8 tf32 with
// 3xTF32 error compensation (hi/lo split) -> fp32-grade accuracy at tensor
// speed. Attention plumbing / LN / swiglu unchanged from the passing R4.
// ---------------------------------------------------------------------------

constexpr int B_    = 4;
constexpr int S_    = 4096;
constexpr int T_    = B_ * S_;        // 16384 tokens
constexpr int D_    = 2048;
constexpr int DFF_  = 8192;
constexpr int H_    = 16;
constexpr int HKV_  = 8;
constexpr int DH_   = 128;
constexpr int RQ_   = 64;
constexpr int RKV_  = 64;
constexpr int KD_   = 64;
constexpr int F_    = 128;            // 2*KD
constexpr int NSPLIT = 8;
constexpr int CHUNK  = S_ / NSPLIT;   // 512

// ------------------------------ scratch (static device globals) -----------
__device__ float g_cq     [(size_t)T_ * RQ_];
__device__ float g_ckv    [(size_t)T_ * RKV_];
__device__ float g_q      [(size_t)T_ * (H_  * DH_)];
__device__ float g_k      [(size_t)T_ * (HKV_* DH_)];
__device__ float g_v      [(size_t)T_ * (HKV_* DH_)];
__device__ float g_phiq   [(size_t)B_ * H_   * S_ * F_];
__device__ float g_phik   [(size_t)B_ * HKV_ * S_ * F_];
__device__ float g_kvpart [(size_t)B_ * HKV_ * NSPLIT * F_ * DH_];
__device__ float g_kvx    [(size_t)B_ * H_   * F_ * DH_];
__device__ float g_z      [(size_t)B_ * HKV_ * F_];
__device__ float g_den    [(size_t)B_ * H_   * S_];
__device__ float g_num    [(size_t)B_ * H_   * S_ * DH_];
__device__ float g_attn   [(size_t)T_ * D_];
__device__ float g_attnout[(size_t)T_ * D_];
__device__ float g_hbuf   [(size_t)T_ * D_];
__device__ float g_gate   [(size_t)T_ * DFF_];
__device__ float g_up     [(size_t)T_ * DFF_];
__device__ float g_ffn    [(size_t)T_ * D_];

// =========================== tensor-core GEMM (3xTF32) =====================
// C[M,N] = A[M,K] @ B[K,N], row-major, fp32 in/out, fp32-grade accuracy via
// hi/lo tf32 split. Requirements: M%128==0, N%128==0, K%8==0,
// C 8B-aligned rows (ldc even). Batched via blockIdx.z strides.

__device__ __forceinline__ float f2tf32(float x) {
    unsigned u;
    asm("cvt.rna.tf32.f32 %0, %1;" : "=r"(u) : "f"(x));
    return __uint_as_float(u);
}

__device__ __forceinline__ void mma8(float4& d, const float* a, const float* b) {
    asm("mma.sync.aligned.m16n8k8.row.col.f32.tf32.tf32.f32 "
        "{%0,%1,%2,%3}, {%4,%5,%6,%7}, {%8,%9}, {%0,%1,%2,%3};"
        : "+f"(d.x), "+f"(d.y), "+f"(d.z), "+f"(d.w)
        : "r"(__float_as_uint(a[0])), "r"(__float_as_uint(a[1])),
          "r"(__float_as_uint(a[2])), "r"(__float_as_uint(a[3])),
          "r"(__float_as_uint(b[0])), "r"(__float_as_uint(b[1])));
}

// smem tile: [k(8)][m or n (128) + pad 8] -> pitch 136 floats.
// Fragment LDS bank = (136*k + idx) % 32 = (8*k + idx%32): tig in 0..3,
// g in 0..7 -> 8*tig+g unique in 0..31 => conflict-free.
__device__ __forceinline__ void compute_step(
    const float (*sAh)[136], const float (*sAl)[136],
    const float (*sBh)[136], const float (*sBl)[136],
    int m0, int n0, int g, int tig, float4 acc[4][4])
{
    float ah[4][4], al[4][4];
#pragma unroll
    for (int im = 0; im < 4; im++) {
        const int r = m0 + im * 16 + g;
        ah[im][0] = sAh[tig    ][r];     ah[im][1] = sAh[tig    ][r + 8];
        ah[im][2] = sAh[tig + 4][r];     ah[im][3] = sAh[tig + 4][r + 8];
        al[im][0] = sAl[tig    ][r];     al[im][1] = sAl[tig    ][r + 8];
        al[im][2] = sAl[tig + 4][r];     al[im][3] = sAl[tig + 4][r + 8];
    }
    float bh[4][2], bl[4][2];
#pragma unroll
    for (int in_ = 0; in_ < 4; in_++) {
        const int nb = n0 + in_ * 8 + g;
        bh[in_][0] = sBh[tig][nb];       bh[in_][1] = sBh[tig + 4][nb];
        bl[in_][0] = sBl[tig][nb];       bl[in_][1] = sBl[tig + 4][nb];
    }
#pragma unroll
    for (int im = 0; im < 4; im++)
#pragma unroll
        for (int in_ = 0; in_ < 4; in_++) {
            mma8(acc[im][in_], ah[im], bh[in_]);   // hi*hi
            mma8(acc[im][in_], ah[im], bl[in_]);   // hi*lo
            mma8(acc[im][in_], al[im], bh[in_]);   // lo*hi
        }
}

__global__ __launch_bounds__(256)
void tgemm3x(const float* __restrict__ A, const float* __restrict__ Bm,
             float* __restrict__ C, int M, int N, int K,
             int lda, int ldb, int ldc,
             long long sA, long long sB, long long sC)
{
    A  += (long long)blockIdx.z * sA;
    Bm += (long long)blockIdx.z * sB;
    C  += (long long)blockIdx.z * sC;

    __shared__ __align__(16) float sAh[2][8][136], sAl[2][8][136];
    __shared__ __align__(16) float sBh[2][8][136], sBl[2][8][136];

    const int tid  = threadIdx.x;
    const int w    = tid >> 5;
    const int lane = tid & 31;
    const int g    = lane >> 2;
    const int tig  = lane & 3;
    const int m0   = (w & 1) * 64;      // warp grid 2 (M) x 4 (N)
    const int n0   = (w >> 1) * 32;
    const int rowBase = blockIdx.y * 128;
    const int colBase = blockIdx.x * 128;

    // loaders: A tile 128x8 (one float4/thread along k), B tile 8x128
    const int aRow = tid >> 1, aK = (tid & 1) << 2;
    const int bK   = tid >> 5, bN = (tid & 31) << 2;
    const float* Ap = A + (size_t)(rowBase + aRow) * lda + aK;
    const float* Bp = Bm + (size_t)bK * ldb + colBase + bN;

    float4 acc[4][4];
#pragma unroll
    for (int i = 0; i < 4; i++)
#pragma unroll
        for (int j = 0; j < 4; j++) acc[i][j] = make_float4(0.f, 0.f, 0.f, 0.f);

    // ---- fill buffer 0 ----
    float4 a4 = *reinterpret_cast<const float4*>(Ap);
    float4 b4 = *reinterpret_cast<const float4*>(Bp);
    {
        float av[4] = {a4.x, a4.y, a4.z, a4.w};
#pragma unroll
        for (int j = 0; j < 4; j++) {
            float hi = f2tf32(av[j]);
            sAh[0][aK + j][aRow] = hi;
            sAl[0][aK + j][aRow] = f2tf32(av[j] - hi);
        }
        float4 bhv, blv;
        bhv.x = f2tf32(b4.x); blv.x = f2tf32(b4.x - bhv.x);
        bhv.y = f2tf32(b4.y); blv.y = f2tf32(b4.y - bhv.y);
        bhv.z = f2tf32(b4.z); blv.z = f2tf32(b4.z - bhv.z);
        bhv.w = f2tf32(b4.w); blv.w = f2tf32(b4.w - bhv.w);
        *reinterpret_cast<float4*>(&sBh[0][bK][bN]) = bhv;
        *reinterpret_cast<float4*>(&sBl[0][bK][bN]) = blv;
    }
    __syncthreads();

    int buf = 0;
    for (int k0 = 8; k0 < K; k0 += 8) {
        // prefetch next tile
        a4 = *reinterpret_cast<const float4*>(Ap + k0);
        b4 = *reinterpret_cast<const float4*>(Bp + (size_t)k0 * ldb);

        compute_step(sAh[buf], sAl[buf], sBh[buf], sBl[buf], m0, n0, g, tig, acc);

        const int nb = buf ^ 1;
        float av[4] = {a4.x, a4.y, a4.z, a4.w};
#pragma unroll
        for (int j = 0; j < 4; j++) {
            float hi = f2tf32(av[j]);
            sAh[nb][aK + j][aRow] = hi;
            sAl[nb][aK + j][aRow] = f2tf32(av[j] - hi);
        }
        float4 bhv, blv;
        bhv.x = f2tf32(b4.x); blv.x = f2tf32(b4.x - bhv.x);
        bhv.y = f2tf32(b4.y); blv.y = f2tf32(b4.y - bhv.y);
        bhv.z = f2tf32(b4.z); blv.z = f2tf32(b4.z - bhv.z);
        bhv.w = f2tf32(b4.w); blv.w = f2tf32(b4.w - bhv.w);
        *reinterpret_cast<float4*>(&sBh[nb][bK][bN]) = bhv;
        *reinterpret_cast<float4*>(&sBl[nb][bK][bN]) = blv;
        __syncthreads();
        buf = nb;
    }
    compute_step(sAh[buf], sAl[buf], sBh[buf], sBl[buf], m0, n0, g, tig, acc);

    // ---- epilogue (no guards: M,N multiples of 128) ----
#pragma unroll
    for (int im = 0; im < 4; im++) {
        const int r = rowBase + m0 + im * 16 + g;
#pragma unroll
        for (int in_ = 0; in_ < 4; in_++) {
            const int cc = colBase + n0 + in_ * 8 + 2 * tig;
            float2 v0 = make_float2(acc[im][in_].x, acc[im][in_].y);
            float2 v1 = make_float2(acc[im][in_].z, acc[im][in_].w);
            *reinterpret_cast<float2*>(C + (size_t)r * ldc + cc)       = v0;
            *reinterpret_cast<float2*>(C + (size_t)(r + 8) * ldc + cc) = v1;
        }
    }
}

// ------------------------------ fp32 SGEMM (small N / ragged shapes) ------
__global__ __launch_bounds__(256, 2)
void sgemm_nn(const float* __restrict__ A, const float* __restrict__ Bm,
              float* __restrict__ C,
              int M, int N, int K, int lda, int ldb, int ldc,
              long long sA, long long sB, long long sC)
{
    A  += (long long)blockIdx.z * sA;
    Bm += (long long)blockIdx.z * sB;
    C  += (long long)blockIdx.z * sC;

    __shared__ float As[8][132];
    __shared__ float Bs[8][128];

    const int tid = threadIdx.x;
    const int tx  = tid & 15;
    const int ty  = tid >> 4;
    const int rowBase = blockIdx.y * 128;
    const int colBase = blockIdx.x * 128;

    const int aRow = tid >> 1;
    const int aCol = (tid & 1) << 2;
    const int bRow = tid >> 5;
    const int bCol = (tid & 31) << 2;

    float acc[8][8];
#pragma unroll
    for (int i = 0; i < 8; i++)
#pragma unroll
        for (int j = 0; j < 8; j++) acc[i][j] = 0.f;

    const int  gArow = rowBase + aRow;
    const bool aInM  = (gArow < M);
    const float* Aptr = A + (size_t)(aInM ? gArow : 0) * lda + aCol;
    const int  gBcol = colBase + bCol;

    for (int k0 = 0; k0 < K; k0 += 8) {
        float4 a4 = make_float4(0.f, 0.f, 0.f, 0.f);
        if (aInM) a4 = *reinterpret_cast<const float4*>(Aptr + k0);
        As[aCol + 0][aRow] = a4.x;
        As[aCol + 1][aRow] = a4.y;
        As[aCol + 2][aRow] = a4.z;
        As[aCol + 3][aRow] = a4.w;

        float4 b4;
        const float* bp = Bm + (size_t)(k0 + bRow) * ldb;
        if (gBcol + 3 < N) {
            b4 = *reinterpret_cast<const float4*>(bp + gBcol);
        } else {
            b4.x = (gBcol + 0 < N) ? bp[gBcol + 0] : 0.f;
            b4.y = (gBcol + 1 < N) ? bp[gBcol + 1] : 0.f;
            b4.z = (gBcol + 2 < N) ? bp[gBcol + 2] : 0.f;
            b4.w = (gBcol + 3 < N) ? bp[gBcol + 3] : 0.f;
        }
        *reinterpret_cast<float4*>(&Bs[bRow][bCol]) = b4;
        __syncthreads();

#pragma unroll
        for (int kk = 0; kk < 8; kk++) {
            float aR[8], bR[8];
#pragma unroll
            for (int i = 0; i < 8; i++) aR[i] = As[kk][ty + 16 * i];
#pragma unroll
            for (int j = 0; j < 8; j++) bR[j] = Bs[kk][tx + 16 * j];
#pragma unroll
            for (int i = 0; i < 8; i++)
#pragma unroll
                for (int j = 0; j < 8; j++) acc[i][j] += aR[i] * bR[j];
        }
        __syncthreads();
    }

#pragma unroll
    for (int i = 0; i < 8; i++) {
        int r = rowBase + ty + 16 * i;
        if (r >= M) continue;
        float* crow = C + (size_t)r * ldc;
#pragma unroll
        for (int j = 0; j < 8; j++) {
            int c = colBase + tx + 16 * j;
            if (c < N) crow[c] = acc[i][j];
        }
    }
}

// ------------------------------ phi (random Fourier features) -------------
__global__ void phi_kernel(const float* __restrict__ qk,
                           const float* __restrict__ omega,
                           float* __restrict__ phi,
                           int nheads, int ldq)
{
    const long long bid = blockIdx.x;             // ((b*nh + h)*S + s)
    const int s = (int)(bid % S_);
    const int h = (int)((bid / S_) % nheads);
    const int b = (int)(bid / ((long long)S_ * nheads));
    const long long t = (long long)b * S_ + s;

    __shared__ float qs[DH_];
    const int k = threadIdx.x;                    // 0..63
    const float* row = qk + (size_t)t * ldq + (size_t)h * DH_;
    qs[k]      = row[k];
    qs[k + 64] = row[k + 64];
    __syncthreads();

    float proj = 0.f;
#pragma unroll 8
    for (int d = 0; d < DH_; d++) proj += qs[d] * omega[d * KD_ + k];

    float sv, cv;
    sincosf(proj, &sv, &cv);
    float* prow = phi + bid * (long long)F_;
    prow[k]      = cv * 0.125f;     // 1/sqrt(64)
    prow[k + 64] = sv * 0.125f;
}

// ------------------------------ z = sum_s phi_k ---------------------------
__global__ void z_kernel(const float* __restrict__ phik, float* __restrict__ z)
{
    const int bh = blockIdx.x;
    const int f  = threadIdx.x;
    const float* p = phik + (size_t)bh * S_ * F_ + f;
    float sum = 0.f;
#pragma unroll 8
    for (int i = 0; i < S_; i++) sum += p[(size_t)i * F_];
    z[bh * F_ + f] = sum;
}

// ------------------------------ kv partial --------------------------------
__global__ __launch_bounds__(256, 2)
void kv_partial(const float* __restrict__ phik, const float* __restrict__ v,
                float* __restrict__ part)
{
    const int bid   = blockIdx.x;
    const int split = bid % NSPLIT;
    const int bh    = bid / NSPLIT;
    const int b     = bh / HKV_;
    const int hk    = bh % HKV_;

    const float* A  = phik + (size_t)bh * S_ * F_ + (size_t)split * CHUNK * F_;
    const float* Bm = v + ((size_t)b * S_ + (size_t)split * CHUNK) * (HKV_ * DH_)
                        + (size_t)hk * DH_;
    float* C = part + (size_t)bid * F_ * DH_;

    __shared__ float As[8][128];
    __shared__ float Bs[8][128];
    const int tid = threadIdx.x;
    const int tx  = tid & 15;
    const int ty  = tid >> 4;
    const int lRow = tid >> 5;
    const int lCol = (tid & 31) << 2;

    float acc[8][8];
#pragma unroll
    for (int i = 0; i < 8; i++)
#pragma unroll
        for (int j = 0; j < 8; j++) acc[i][j] = 0.f;

    for (int k0 = 0; k0 < CHUNK; k0 += 8) {
        *reinterpret_cast<float4*>(&As[lRow][lCol]) =
            *reinterpret_cast<const float4*>(A + (size_t)(k0 + lRow) * F_ + lCol);
        *reinterpret_cast<float4*>(&Bs[lRow][lCol]) =
            *reinterpret_cast<const float4*>(Bm + (size_t)(k0 + lRow) * (HKV_ * DH_) + lCol);
        __syncthreads();
#pragma unroll
        for (int kk = 0; kk < 8; kk++) {
            float aR[8], bR[8];
#pragma unroll
            for (int i = 0; i < 8; i++) aR[i] = As[kk][ty + 16 * i];
#pragma unroll
            for (int j = 0; j < 8; j++) bR[j] = Bs[kk][tx + 16 * j];
#pragma unroll
            for (int i = 0; i < 8; i++)
#pragma unroll
                for (int j = 0; j < 8; j++) acc[i][j] += aR[i] * bR[j];
        }
        __syncthreads();
    }
#pragma unroll
    for (int i = 0; i < 8; i++)
#pragma unroll
        for (int j = 0; j < 8; j++)
            C[(size_t)(ty + 16 * i) * DH_ + (tx + 16 * j)] = acc[i][j];
}

// ------------------------------ reduce splits + GQA expand ----------------
__global__ void kv_reduce_expand(const float* __restrict__ part,
                                 float* __restrict__ kvx)
{
    const long long n = (long long)B_ * H_ * F_ * DH_;
    long long i = (long long)blockIdx.x * blockDim.x + threadIdx.x;
    if (i >= n) return;
    const int fd = (int)(i & (F_ * DH_ - 1));
    const int h  = (int)((i >> 14) & (H_ - 1));
    const int b  = (int)(i >> 18);
    const int bh = b * HKV_ + (h >> 1);
    float s = 0.f;
#pragma unroll
    for (int sp = 0; sp < NSPLIT; sp++)
        s += part[(((size_t)bh * NSPLIT + sp) << 14) + fd];
    kvx[i] = s;
}

// ------------------------------ den ---------------------------------------
__global__ void den_kernel(const float* __restrict__ phiq,
                           const float* __restrict__ z,
                           float* __restrict__ den)
{
    const long long warp = ((long long)blockIdx.x * blockDim.x + threadIdx.x) >> 5;
    const int lane = threadIdx.x & 31;
    if (warp >= (long long)B_ * H_ * S_) return;
    const int h = (int)((warp / S_) % H_);
    const int b = (int)(warp / ((long long)S_ * H_));
    const float* zp = z + (size_t)(b * HKV_ + (h >> 1)) * F_;
    const float* pr = phiq + warp * (long long)F_;
    float sum = 0.f;
#pragma unroll
    for (int j = 0; j < 4; j++) {
        int f = lane + 32 * j;
        sum += pr[f] * zp[f];
    }
#pragma unroll
    for (int o = 16; o; o >>= 1) sum += __shfl_xor_sync(0xffffffffu, sum, o);
    if (lane == 0) den[warp] = sum;
}

// ------------------------------ attn assembly -----------------------------
__global__ void attn_assemble(const float* __restrict__ num,
                              const float* __restrict__ den,
                              float* __restrict__ attn)
{
    const long long n = (long long)B_ * H_ * S_ * DH_;
    long long i = (long long)blockIdx.x * blockDim.x + threadIdx.x;
    if (i >= n) return;
    const int d = (int)(i & (DH_ - 1));
    const long long r = i >> 7;
    const int s = (int)(r & (S_ - 1));
    const int h = (int)((r >> 12) & (H_ - 1));
    const int b = (int)(r >> 16);
    const float val = num[i] / (den[r] + 1e-6f);
    attn[((size_t)b * S_ + s) * (size_t)D_ + (size_t)h * DH_ + d] = val;
}

// ------------------------------ out = LN(a+b)*g + beta --------------------
__global__ __launch_bounds__(256)
void add_ln_kernel(const float* __restrict__ a, const float* __restrict__ bb,
                   const float* __restrict__ g, const float* __restrict__ beta,
                   float* __restrict__ out)
{
    __shared__ float sh[10];
    const size_t row = blockIdx.x;
    const float* ar = a  + row * D_;
    const float* br = bb + row * D_;
    const int tid = threadIdx.x;

    float loc[8];
    float sum = 0.f;
#pragma unroll
    for (int j = 0; j < 8; j++) {
        int c = tid + 256 * j;
        float v = ar[c] + br[c];
        loc[j] = v;
        sum += v;
    }
#pragma unroll
    for (int o = 16; o; o >>= 1) sum += __shfl_xor_sync(0xffffffffu, sum, o);
    if ((tid & 31) == 0) sh[tid >> 5] = sum;
    __syncthreads();
    if (tid == 0) {
        float s = 0.f;
        for (int i = 0; i < 8; i++) s += sh[i];
        sh[8] = s;
    }
    __syncthreads();
    const float mu = sh[8] * (1.f / D_);

    float sq = 0.f;
#pragma unroll
    for (int j = 0; j < 8; j++) {
        float dv = loc[j] - mu;
        sq += dv * dv;
    }
    __syncthreads();
#pragma unroll
    for (int o = 16; o; o >>= 1) sq += __shfl_xor_sync(0xffffffffu, sq, o);
    if ((tid & 31) == 0) sh[tid >> 5] = sq;
    __syncthreads();
    if (tid == 0) {
        float s = 0.f;
        for (int i = 0; i < 8; i++) s += sh[i];
        sh[9] = s;
    }
    __syncthreads();
    const float rstd = rsqrtf(sh[9] * (1.f / D_) + 1e-5f);

    float* orow = out + row * D_;
#pragma unroll
    for (int j = 0; j < 8; j++) {
        int c = tid + 256 * j;
        orow[c] = (loc[j] - mu) * rstd * g[c] + beta[c];
    }
}

// ------------------------------ gate *= silu(up) --------------------------
__global__ void swiglu_kernel(float* __restrict__ gate,
                              const float* __restrict__ up)
{
    const long long n = (long long)T_ * DFF_;
    long long i = (long long)blockIdx.x * blockDim.x + threadIdx.x;
    if (i >= n) return;
    const float u = up[i];
    const float s = u / (1.f + expf(-u));
    gate[i] = gate[i] * s;
}

// ---------------------------------------------------------------------------
extern "C" void kernel_launch(void* const* d_in, const int* in_sizes, int n_in,
                              void* d_out, int out_size)
{
    const float* x      = (const float*)d_in[0];
    const float* W_dq   = (const float*)d_in[1];
    const float* W_uq   = (const float*)d_in[2];
    const float* W_dkv  = (const float*)d_in[3];
    const float* W_uk   = (const float*)d_in[4];
    const float* W_uv   = (const float*)d_in[5];
    const float* omega  = (const float*)d_in[6];
    const float* W_o    = (const float*)d_in[7];
    const float* ln1_g  = (const float*)d_in[8];
    const float* ln1_b  = (const float*)d_in[9];
    const float* gate_W = (const float*)d_in[10];
    const float* up_W   = (const float*)d_in[11];
    const float* down_W = (const float*)d_in[12];
    const float* ln2_g  = (const float*)d_in[13];
    const float* ln2_b  = (const float*)d_in[14];
    float* out = (float*)d_out;

    float *cq, *ckv, *q, *k, *v, *phiq, *phik, *kvpart, *kvx, *z, *den, *num;
    float *attn, *attnout, *hbuf, *gate, *up, *ffn;
    cudaGetSymbolAddress((void**)&cq,      g_cq);
    cudaGetSymbolAddress((void**)&ckv,     g_ckv);
    cudaGetSymbolAddress((void**)&q,       g_q);
    cudaGetSymbolAddress((void**)&k,       g_k);
    cudaGetSymbolAddress((void**)&v,       g_v);
    cudaGetSymbolAddress((void**)&phiq,    g_phiq);
    cudaGetSymbolAddress((void**)&phik,    g_phik);
    cudaGetSymbolAddress((void**)&kvpart,  g_kvpart);
    cudaGetSymbolAddress((void**)&kvx,     g_kvx);
    cudaGetSymbolAddress((void**)&z,       g_z);
    cudaGetSymbolAddress((void**)&den,     g_den);
    cudaGetSymbolAddress((void**)&num,     g_num);
    cudaGetSymbolAddress((void**)&attn,    g_attn);
    cudaGetSymbolAddress((void**)&attnout, g_attnout);
    cudaGetSymbolAddress((void**)&hbuf,    g_hbuf);
    cudaGetSymbolAddress((void**)&gate,    g_gate);
    cudaGetSymbolAddress((void**)&up,      g_up);
    cudaGetSymbolAddress((void**)&ffn,     g_ffn);

    // --- low-rank down-projections (N=64 -> keep fp32 sgemm) ---
    sgemm_nn<<<dim3(1, 128, 1), 256>>>(x,  W_dq,  cq,  T_, RQ_,  D_, D_, RQ_,  RQ_, 0, 0, 0);
    sgemm_nn<<<dim3(1, 128, 1), 256>>>(x,  W_dkv, ckv, T_, RKV_, D_, D_, RKV_, RKV_, 0, 0, 0);

    // --- up-projections on tensor cores (K=64) ---
    tgemm3x<<<dim3(16, 128, 1), 256>>>(cq,  W_uq, q, T_, H_ * DH_,  RQ_,
                                       RQ_,  H_ * DH_,  H_ * DH_, 0, 0, 0);
    tgemm3x<<<dim3(8, 128, 1), 256>>>(ckv, W_uk, k, T_, HKV_ * DH_, RKV_,
                                      RKV_, HKV_ * DH_, HKV_ * DH_, 0, 0, 0);
    tgemm3x<<<dim3(8, 128, 1), 256>>>(ckv, W_uv, v, T_, HKV_ * DH_, RKV_,
                                      RKV_, HKV_ * DH_, HKV_ * DH_, 0, 0, 0);

    // --- random Fourier features ---
    phi_kernel<<<B_ * H_   * S_, 64>>>(q, omega, phiq, H_,   H_   * DH_);
    phi_kernel<<<B_ * HKV_ * S_, 64>>>(k, omega, phik, HKV_, HKV_ * DH_);

    // --- linear attention state ---
    z_kernel<<<B_ * HKV_, 128>>>(phik, z);
    kv_partial<<<B_ * HKV_ * NSPLIT, 256>>>(phik, v, kvpart);
    kv_reduce_expand<<<(B_ * H_ * F_ * DH_ + 255) / 256, 256>>>(kvpart, kvx);
    den_kernel<<<(B_ * H_ * S_) / 8, 256>>>(phiq, z, den);

    // num = phi_q @ kv (batched over B*H) on tensor cores
    tgemm3x<<<dim3(1, 32, B_ * H_), 256>>>(phiq, kvx, num,
                                           S_, DH_, F_, F_, DH_, DH_,
                                           (long long)S_ * F_,
                                           (long long)F_ * DH_,
                                           (long long)S_ * DH_);
    attn_assemble<<<(B_ * H_ * S_ * DH_ + 255) / 256, 256>>>(num, den, attn);

    // --- output projection + residual/LN ---
    tgemm3x<<<dim3(16, 128, 1), 256>>>(attn, W_o, attnout, T_, D_, D_,
                                       D_, D_, D_, 0, 0, 0);
    add_ln_kernel<<<T_, 256>>>(x, attnout, ln1_g, ln1_b, hbuf);

    // --- SwiGLU FFN on tensor cores ---
    tgemm3x<<<dim3(64, 128, 1), 256>>>(hbuf, gate_W, gate, T_, DFF_, D_,
                                       D_, DFF_, DFF_, 0, 0, 0);
    tgemm3x<<<dim3(64, 128, 1), 256>>>(hbuf, up_W,   up,   T_, DFF_, D_,
                                       D_, DFF_, DFF_, 0, 0, 0);
    swiglu_kernel<<<(int)(((long long)T_ * DFF_ + 255) / 256), 256>>>(gate, up);
    tgemm3x<<<dim3(16, 128, 1), 256>>>(gate, down_W, ffn, T_, D_, DFF_,
                                       DFF_, D_, D_, 0, 0, 0);

    // --- final residual/LN -> output ---
    add_ln_kernel<<<T_, 256>>>(hbuf, ffn, ln2_g, ln2_b, out);
}

// round 12
// speedup vs baseline: 1.0008x; 1.0007x over previous
#include <cuda_runtime.h>
#include <math.h>

// ---------------------------------------------------------------------------
// MLGKA layer. R5: big GEMMs on tensor cores via mma.sync m16n8k8 tf32 with
// 3xTF32 error compensation (hi/lo split) -> fp32-grade accuracy at tensor
// speed. Attention plumbing / LN / swiglu unchanged from the passing R4.
// ---------------------------------------------------------------------------

constexpr int B_    = 4;
constexpr int S_    = 4096;
constexpr int T_    = B_ * S_;        // 16384 tokens
constexpr int D_    = 2048;
constexpr int DFF_  = 8192;
constexpr int H_    = 16;
constexpr int HKV_  = 8;
constexpr int DH_   = 128;
constexpr int RQ_   = 64;
constexpr int RKV_  = 64;
constexpr int KD_   = 64;
constexpr int F_    = 128;            // 2*KD
constexpr int NSPLIT = 8;
constexpr int CHUNK  = S_ / NSPLIT;   // 512

// ------------------------------ scratch (static device globals) -----------
__device__ float g_cq     [(size_t)T_ * RQ_];
__device__ float g_ckv    [(size_t)T_ * RKV_];
__device__ float g_q      [(size_t)T_ * (H_  * DH_)];
__device__ float g_k      [(size_t)T_ * (HKV_* DH_)];
__device__ float g_v      [(size_t)T_ * (HKV_* DH_)];
__device__ float g_phiq   [(size_t)B_ * H_   * S_ * F_];
__device__ float g_phik   [(size_t)B_ * HKV_ * S_ * F_];
__device__ float g_kvpart [(size_t)B_ * HKV_ * NSPLIT * F_ * DH_];
__device__ float g_kvx    [(size_t)B_ * H_   * F_ * DH_];
__device__ float g_z      [(size_t)B_ * HKV_ * F_];
__device__ float g_den    [(size_t)B_ * H_   * S_];
__device__ float g_num    [(size_t)B_ * H_   * S_ * DH_];
__device__ float g_attn   [(size_t)T_ * D_];
__device__ float g_attnout[(size_t)T_ * D_];
__device__ float g_hbuf   [(size_t)T_ * D_];
__device__ float g_gate   [(size_t)T_ * DFF_];
__device__ float g_up     [(size_t)T_ * DFF_];
__device__ float g_ffn    [(size_t)T_ * D_];

// =========================== tensor-core GEMM (3xTF32) =====================
// C[M,N] = A[M,K] @ B[K,N], row-major, fp32 in/out, fp32-grade accuracy via
// hi/lo tf32 split. Requirements: M%128==0, N%128==0, K%8==0,
// C 8B-aligned rows (ldc even). Batched via blockIdx.z strides.

__device__ __forceinline__ float f2tf32(float x) {
    unsigned u;
    asm("cvt.rna.tf32.f32 %0, %1;" : "=r"(u) : "f"(x));
    return __uint_as_float(u);
}

__device__ __forceinline__ void mma8(float4& d, const float* a, const float* b) {
    asm("mma.sync.aligned.m16n8k8.row.col.f32.tf32.tf32.f32 "
        "{%0,%1,%2,%3}, {%4,%5,%6,%7}, {%8,%9}, {%0,%1,%2,%3};"
        : "+f"(d.x), "+f"(d.y), "+f"(d.z), "+f"(d.w)
        : "r"(__float_as_uint(a[0])), "r"(__float_as_uint(a[1])),
          "r"(__float_as_uint(a[2])), "r"(__float_as_uint(a[3])),
          "r"(__float_as_uint(b[0])), "r"(__float_as_uint(b[1])));
}

// smem tile: [k(8)][m or n (128) + pad 8] -> pitch 136 floats.
// Fragment LDS bank = (136*k + idx) % 32 = (8*k + idx%32): tig in 0..3,
// g in 0..7 -> 8*tig+g unique in 0..31 => conflict-free.
__device__ __forceinline__ void compute_step(
    const float (*sAh)[136], const float (*sAl)[136],
    const float (*sBh)[136], const float (*sBl)[136],
    int m0, int n0, int g, int tig, float4 acc[4][4])
{
    float ah[4][4], al[4][4];
#pragma unroll
    for (int im = 0; im < 4; im++) {
        const int r = m0 + im * 16 + g;
        ah[im][0] = sAh[tig    ][r];     ah[im][1] = sAh[tig    ][r + 8];
        ah[im][2] = sAh[tig + 4][r];     ah[im][3] = sAh[tig + 4][r + 8];
        al[im][0] = sAl[tig    ][r];     al[im][1] = sAl[tig    ][r + 8];
        al[im][2] = sAl[tig + 4][r];     al[im][3] = sAl[tig + 4][r + 8];
    }
    float bh[4][2], bl[4][2];
#pragma unroll
    for (int in_ = 0; in_ < 4; in_++) {
        const int nb = n0 + in_ * 8 + g;
        bh[in_][0] = sBh[tig][nb];       bh[in_][1] = sBh[tig + 4][nb];
        bl[in_][0] = sBl[tig][nb];       bl[in_][1] = sBl[tig + 4][nb];
    }
#pragma unroll
    for (int im = 0; im < 4; im++)
#pragma unroll
        for (int in_ = 0; in_ < 4; in_++) {
            mma8(acc[im][in_], ah[im], bh[in_]);   // hi*hi
            mma8(acc[im][in_], ah[im], bl[in_]);   // hi*lo
            mma8(acc[im][in_], al[im], bh[in_]);   // lo*hi
        }
}

__global__ __launch_bounds__(256)
void tgemm3x(const float* __restrict__ A, const float* __restrict__ Bm,
             float* __restrict__ C, int M, int N, int K,
             int lda, int ldb, int ldc,
             long long sA, long long sB, long long sC)
{
    A  += (long long)blockIdx.z * sA;
    Bm += (long long)blockIdx.z * sB;
    C  += (long long)blockIdx.z * sC;

    __shared__ __align__(16) float sAh[2][8][136], sAl[2][8][136];
    __shared__ __align__(16) float sBh[2][8][136], sBl[2][8][136];

    const int tid  = threadIdx.x;
    const int w    = tid >> 5;
    const int lane = tid & 31;
    const int g    = lane >> 2;
    const int tig  = lane & 3;
    const int m0   = (w & 1) * 64;      // warp grid 2 (M) x 4 (N)
    const int n0   = (w >> 1) * 32;
    const int rowBase = blockIdx.y * 128;
    const int colBase = blockIdx.x * 128;

    // loaders: A tile 128x8 (one float4/thread along k), B tile 8x128
    const int aRow = tid >> 1, aK = (tid & 1) << 2;
    const int bK   = tid >> 5, bN = (tid & 31) << 2;
    const float* Ap = A + (size_t)(rowBase + aRow) * lda + aK;
    const float* Bp = Bm + (size_t)bK * ldb + colBase + bN;

    float4 acc[4][4];
#pragma unroll
    for (int i = 0; i < 4; i++)
#pragma unroll
        for (int j = 0; j < 4; j++) acc[i][j] = make_float4(0.f, 0.f, 0.f, 0.f);

    // ---- fill buffer 0 ----
    float4 a4 = *reinterpret_cast<const float4*>(Ap);
    float4 b4 = *reinterpret_cast<const float4*>(Bp);
    {
        float av[4] = {a4.x, a4.y, a4.z, a4.w};
#pragma unroll
        for (int j = 0; j < 4; j++) {
            float hi = f2tf32(av[j]);
            sAh[0][aK + j][aRow] = hi;
            sAl[0][aK + j][aRow] = f2tf32(av[j] - hi);
        }
        float4 bhv, blv;
        bhv.x = f2tf32(b4.x); blv.x = f2tf32(b4.x - bhv.x);
        bhv.y = f2tf32(b4.y); blv.y = f2tf32(b4.y - bhv.y);
        bhv.z = f2tf32(b4.z); blv.z = f2tf32(b4.z - bhv.z);
        bhv.w = f2tf32(b4.w); blv.w = f2tf32(b4.w - bhv.w);
        *reinterpret_cast<float4*>(&sBh[0][bK][bN]) = bhv;
        *reinterpret_cast<float4*>(&sBl[0][bK][bN]) = blv;
    }
    __syncthreads();

    int buf = 0;
    for (int k0 = 8; k0 < K; k0 += 8) {
        // prefetch next tile
        a4 = *reinterpret_cast<const float4*>(Ap + k0);
        b4 = *reinterpret_cast<const float4*>(Bp + (size_t)k0 * ldb);

        compute_step(sAh[buf], sAl[buf], sBh[buf], sBl[buf], m0, n0, g, tig, acc);

        const int nb = buf ^ 1;
        float av[4] = {a4.x, a4.y, a4.z, a4.w};
#pragma unroll
        for (int j = 0; j < 4; j++) {
            float hi = f2tf32(av[j]);
            sAh[nb][aK + j][aRow] = hi;
            sAl[nb][aK + j][aRow] = f2tf32(av[j] - hi);
        }
        float4 bhv, blv;
        bhv.x = f2tf32(b4.x); blv.x = f2tf32(b4.x - bhv.x);
        bhv.y = f2tf32(b4.y); blv.y = f2tf32(b4.y - bhv.y);
        bhv.z = f2tf32(b4.z); blv.z = f2tf32(b4.z - bhv.z);
        bhv.w = f2tf32(b4.w); blv.w = f2tf32(b4.w - bhv.w);
        *reinterpret_cast<float4*>(&sBh[nb][bK][bN]) = bhv;
        *reinterpret_cast<float4*>(&sBl[nb][bK][bN]) = blv;
        __syncthreads();
        buf = nb;
    }
    compute_step(sAh[buf], sAl[buf], sBh[buf], sBl[buf], m0, n0, g, tig, acc);

    // ---- epilogue (no guards: M,N multiples of 128) ----
#pragma unroll
    for (int im = 0; im < 4; im++) {
        const int r = rowBase + m0 + im * 16 + g;
#pragma unroll
        for (int in_ = 0; in_ < 4; in_++) {
            const int cc = colBase + n0 + in_ * 8 + 2 * tig;
            float2 v0 = make_float2(acc[im][in_].x, acc[im][in_].y);
            float2 v1 = make_float2(acc[im][in_].z, acc[im][in_].w);
            *reinterpret_cast<float2*>(C + (size_t)r * ldc + cc)       = v0;
            *reinterpret_cast<float2*>(C + (size_t)(r + 8) * ldc + cc) = v1;
        }
    }
}

// ------------------------------ fp32 SGEMM (small N / ragged shapes) ------
__global__ __launch_bounds__(256, 2)
void sgemm_nn(const float* __restrict__ A, const float* __restrict__ Bm,
              float* __restrict__ C,
              int M, int N, int K, int lda, int ldb, int ldc,
              long long sA, long long sB, long long sC)
{
    A  += (long long)blockIdx.z * sA;
    Bm += (long long)blockIdx.z * sB;
    C  += (long long)blockIdx.z * sC;

    __shared__ float As[8][132];
    __shared__ float Bs[8][128];

    const int tid = threadIdx.x;
    const int tx  = tid & 15;
    const int ty  = tid >> 4;
    const int rowBase = blockIdx.y * 128;
    const int colBase = blockIdx.x * 128;

    const int aRow = tid >> 1;
    const int aCol = (tid & 1) << 2;
    const int bRow = tid >> 5;
    const int bCol = (tid & 31) << 2;

    float acc[8][8];
#pragma unroll
    for (int i = 0; i < 8; i++)
#pragma unroll
        for (int j = 0; j < 8; j++) acc[i][j] = 0.f;

    const int  gArow = rowBase + aRow;
    const bool aInM  = (gArow < M);
    const float* Aptr = A + (size_t)(aInM ? gArow : 0) * lda + aCol;
    const int  gBcol = colBase + bCol;

    for (int k0 = 0; k0 < K; k0 += 8) {
        float4 a4 = make_float4(0.f, 0.f, 0.f, 0.f);
        if (aInM) a4 = *reinterpret_cast<const float4*>(Aptr + k0);
        As[aCol + 0][aRow] = a4.x;
        As[aCol + 1][aRow] = a4.y;
        As[aCol + 2][aRow] = a4.z;
        As[aCol + 3][aRow] = a4.w;

        float4 b4;
        const float* bp = Bm + (size_t)(k0 + bRow) * ldb;
        if (gBcol + 3 < N) {
            b4 = *reinterpret_cast<const float4*>(bp + gBcol);
        } else {
            b4.x = (gBcol + 0 < N) ? bp[gBcol + 0] : 0.f;
            b4.y = (gBcol + 1 < N) ? bp[gBcol + 1] : 0.f;
            b4.z = (gBcol + 2 < N) ? bp[gBcol + 2] : 0.f;
            b4.w = (gBcol + 3 < N) ? bp[gBcol + 3] : 0.f;
        }
        *reinterpret_cast<float4*>(&Bs[bRow][bCol]) = b4;
        __syncthreads();

#pragma unroll
        for (int kk = 0; kk < 8; kk++) {
            float aR[8], bR[8];
#pragma unroll
            for (int i = 0; i < 8; i++) aR[i] = As[kk][ty + 16 * i];
#pragma unroll
            for (int j = 0; j < 8; j++) bR[j] = Bs[kk][tx + 16 * j];
#pragma unroll
            for (int i = 0; i < 8; i++)
#pragma unroll
                for (int j = 0; j < 8; j++) acc[i][j] += aR[i] * bR[j];
        }
        __syncthreads();
    }

#pragma unroll
    for (int i = 0; i < 8; i++) {
        int r = rowBase + ty + 16 * i;
        if (r >= M) continue;
        float* crow = C + (size_t)r * ldc;
#pragma unroll
        for (int j = 0; j < 8; j++) {
            int c = colBase + tx + 16 * j;
            if (c < N) crow[c] = acc[i][j];
        }
    }
}

// ------------------------------ phi (random Fourier features) -------------
__global__ void phi_kernel(const float* __restrict__ qk,
                           const float* __restrict__ omega,
                           float* __restrict__ phi,
                           int nheads, int ldq)
{
    const long long bid = blockIdx.x;             // ((b*nh + h)*S + s)
    const int s = (int)(bid % S_);
    const int h = (int)((bid / S_) % nheads);
    const int b = (int)(bid / ((long long)S_ * nheads));
    const long long t = (long long)b * S_ + s;

    __shared__ float qs[DH_];
    const int k = threadIdx.x;                    // 0..63
    const float* row = qk + (size_t)t * ldq + (size_t)h * DH_;
    qs[k]      = row[k];
    qs[k + 64] = row[k + 64];
    __syncthreads();

    float proj = 0.f;
#pragma unroll 8
    for (int d = 0; d < DH_; d++) proj += qs[d] * omega[d * KD_ + k];

    float sv, cv;
    sincosf(proj, &sv, &cv);
    float* prow = phi + bid * (long long)F_;
    prow[k]      = cv * 0.125f;     // 1/sqrt(64)
    prow[k + 64] = sv * 0.125f;
}

// ------------------------------ z = sum_s phi_k ---------------------------
__global__ void z_kernel(const float* __restrict__ phik, float* __restrict__ z)
{
    const int bh = blockIdx.x;
    const int f  = threadIdx.x;
    const float* p = phik + (size_t)bh * S_ * F_ + f;
    float sum = 0.f;
#pragma unroll 8
    for (int i = 0; i < S_; i++) sum += p[(size_t)i * F_];
    z[bh * F_ + f] = sum;
}

// ------------------------------ kv partial --------------------------------
__global__ __launch_bounds__(256, 2)
void kv_partial(const float* __restrict__ phik, const float* __restrict__ v,
                float* __restrict__ part)
{
    const int bid   = blockIdx.x;
    const int split = bid % NSPLIT;
    const int bh    = bid / NSPLIT;
    const int b     = bh / HKV_;
    const int hk    = bh % HKV_;

    const float* A  = phik + (size_t)bh * S_ * F_ + (size_t)split * CHUNK * F_;
    const float* Bm = v + ((size_t)b * S_ + (size_t)split * CHUNK) * (HKV_ * DH_)
                        + (size_t)hk * DH_;
    float* C = part + (size_t)bid * F_ * DH_;

    __shared__ float As[8][128];
    __shared__ float Bs[8][128];
    const int tid = threadIdx.x;
    const int tx  = tid & 15;
    const int ty  = tid >> 4;
    const int lRow = tid >> 5;
    const int lCol = (tid & 31) << 2;

    float acc[8][8];
#pragma unroll
    for (int i = 0; i < 8; i++)
#pragma unroll
        for (int j = 0; j < 8; j++) acc[i][j] = 0.f;

    for (int k0 = 0; k0 < CHUNK; k0 += 8) {
        *reinterpret_cast<float4*>(&As[lRow][lCol]) =
            *reinterpret_cast<const float4*>(A + (size_t)(k0 + lRow) * F_ + lCol);
        *reinterpret_cast<float4*>(&Bs[lRow][lCol]) =
            *reinterpret_cast<const float4*>(Bm + (size_t)(k0 + lRow) * (HKV_ * DH_) + lCol);
        __syncthreads();
#pragma unroll
        for (int kk = 0; kk < 8; kk++) {
            float aR[8], bR[8];
#pragma unroll
            for (int i = 0; i < 8; i++) aR[i] = As[kk][ty + 16 * i];
#pragma unroll
            for (int j = 0; j < 8; j++) bR[j] = Bs[kk][tx + 16 * j];
#pragma unroll
            for (int i = 0; i < 8; i++)
#pragma unroll
                for (int j = 0; j < 8; j++) acc[i][j] += aR[i] * bR[j];
        }
        __syncthreads();
    }
#pragma unroll
    for (int i = 0; i < 8; i++)
#pragma unroll
        for (int j = 0; j < 8; j++)
            C[(size_t)(ty + 16 * i) * DH_ + (tx + 16 * j)] = acc[i][j];
}

// ------------------------------ reduce splits + GQA expand ----------------
__global__ void kv_reduce_expand(const float* __restrict__ part,
                                 float* __restrict__ kvx)
{
    const long long n = (long long)B_ * H_ * F_ * DH_;
    long long i = (long long)blockIdx.x * blockDim.x + threadIdx.x;
    if (i >= n) return;
    const int fd = (int)(i & (F_ * DH_ - 1));
    const int h  = (int)((i >> 14) & (H_ - 1));
    const int b  = (int)(i >> 18);
    const int bh = b * HKV_ + (h >> 1);
    float s = 0.f;
#pragma unroll
    for (int sp = 0; sp < NSPLIT; sp++)
        s += part[(((size_t)bh * NSPLIT + sp) << 14) + fd];
    kvx[i] = s;
}

// ------------------------------ den ---------------------------------------
__global__ void den_kernel(const float* __restrict__ phiq,
                           const float* __restrict__ z,
                           float* __restrict__ den)
{
    const long long warp = ((long long)blockIdx.x * blockDim.x + threadIdx.x) >> 5;
    const int lane = threadIdx.x & 31;
    if (warp >= (long long)B_ * H_ * S_) return;
    const int h = (int)((warp / S_) % H_);
    const int b = (int)(warp / ((long long)S_ * H_));
    const float* zp = z + (size_t)(b * HKV_ + (h >> 1)) * F_;
    const float* pr = phiq + warp * (long long)F_;
    float sum = 0.f;
#pragma unroll
    for (int j = 0; j < 4; j++) {
        int f = lane + 32 * j;
        sum += pr[f] * zp[f];
    }
#pragma unroll
    for (int o = 16; o; o >>= 1) sum += __shfl_xor_sync(0xffffffffu, sum, o);
    if (lane == 0) den[warp] = sum;
}

// ------------------------------ attn assembly -----------------------------
__global__ void attn_assemble(const float* __restrict__ num,
                              const float* __restrict__ den,
                              float* __restrict__ attn)
{
    const long long n = (long long)B_ * H_ * S_ * DH_;
    long long i = (long long)blockIdx.x * blockDim.x + threadIdx.x;
    if (i >= n) return;
    const int d = (int)(i & (DH_ - 1));
    const long long r = i >> 7;
    const int s = (int)(r & (S_ - 1));
    const int h = (int)((r >> 12) & (H_ - 1));
    const int b = (int)(r >> 16);
    const float val = num[i] / (den[r] + 1e-6f);
    attn[((size_t)b * S_ + s) * (size_t)D_ + (size_t)h * DH_ + d] = val;
}

// ------------------------------ out = LN(a+b)*g + beta --------------------
__global__ __launch_bounds__(256)
void add_ln_kernel(const float* __restrict__ a, const float* __restrict__ bb,
                   const float* __restrict__ g, const float* __restrict__ beta,
                   float* __restrict__ out)
{
    __shared__ float sh[10];
    const size_t row = blockIdx.x;
    const float* ar = a  + row * D_;
    const float* br = bb + row * D_;
    const int tid = threadIdx.x;

    float loc[8];
    float sum = 0.f;
#pragma unroll
    for (int j = 0; j < 8; j++) {
        int c = tid + 256 * j;
        float v = ar[c] + br[c];
        loc[j] = v;
        sum += v;
    }
#pragma unroll
    for (int o = 16; o; o >>= 1) sum += __shfl_xor_sync(0xffffffffu, sum, o);
    if ((tid & 31) == 0) sh[tid >> 5] = sum;
    __syncthreads();
    if (tid == 0) {
        float s = 0.f;
        for (int i = 0; i < 8; i++) s += sh[i];
        sh[8] = s;
    }
    __syncthreads();
    const float mu = sh[8] * (1.f / D_);

    float sq = 0.f;
#pragma unroll
    for (int j = 0; j < 8; j++) {
        float dv = loc[j] - mu;
        sq += dv * dv;
    }
    __syncthreads();
#pragma unroll
    for (int o = 16; o; o >>= 1) sq += __shfl_xor_sync(0xffffffffu, sq, o);
    if ((tid & 31) == 0) sh[tid >> 5] = sq;
    __syncthreads();
    if (tid == 0) {
        float s = 0.f;
        for (int i = 0; i < 8; i++) s += sh[i];
        sh[9] = s;
    }
    __syncthreads();
    const float rstd = rsqrtf(sh[9] * (1.f / D_) + 1e-5f);

    float* orow = out + row * D_;
#pragma unroll
    for (int j = 0; j < 8; j++) {
        int c = tid + 256 * j;
        orow[c] = (loc[j] - mu) * rstd * g[c] + beta[c];
    }
}

// ------------------------------ gate *= silu(up) --------------------------
__global__ void swiglu_kernel(float* __restrict__ gate,
                              const float* __restrict__ up)
{
    const long long n = (long long)T_ * DFF_;
    long long i = (long long)blockIdx.x * blockDim.x + threadIdx.x;
    if (i >= n) return;
    const float u = up[i];
    const float s = u / (1.f + expf(-u));
    gate[i] = gate[i] * s;
}

// ---------------------------------------------------------------------------
extern "C" void kernel_launch(void* const* d_in, const int* in_sizes, int n_in,
                              void* d_out, int out_size)
{
    const float* x      = (const float*)d_in[0];
    const float* W_dq   = (const float*)d_in[1];
    const float* W_uq   = (const float*)d_in[2];
    const float* W_dkv  = (const float*)d_in[3];
    const float* W_uk   = (const float*)d_in[4];
    const float* W_uv   = (const float*)d_in[5];
    const float* omega  = (const float*)d_in[6];
    const float* W_o    = (const float*)d_in[7];
    const float* ln1_g  = (const float*)d_in[8];
    const float* ln1_b  = (const float*)d_in[9];
    const float* gate_W = (const float*)d_in[10];
    const float* up_W   = (const float*)d_in[11];
    const float* down_W = (const float*)d_in[12];
    const float* ln2_g  = (const float*)d_in[13];
    const float* ln2_b  = (const float*)d_in[14];
    float* out = (float*)d_out;

    float *cq, *ckv, *q, *k, *v, *phiq, *phik, *kvpart, *kvx, *z, *den, *num;
    float *attn, *attnout, *hbuf, *gate, *up, *ffn;
    cudaGetSymbolAddress((void**)&cq,      g_cq);
    cudaGetSymbolAddress((void**)&ckv,     g_ckv);
    cudaGetSymbolAddress((void**)&q,       g_q);
    cudaGetSymbolAddress((void**)&k,       g_k);
    cudaGetSymbolAddress((void**)&v,       g_v);
    cudaGetSymbolAddress((void**)&phiq,    g_phiq);
    cudaGetSymbolAddress((void**)&phik,    g_phik);
    cudaGetSymbolAddress((void**)&kvpart,  g_kvpart);
    cudaGetSymbolAddress((void**)&kvx,     g_kvx);
    cudaGetSymbolAddress((void**)&z,       g_z);
    cudaGetSymbolAddress((void**)&den,     g_den);
    cudaGetSymbolAddress((void**)&num,     g_num);
    cudaGetSymbolAddress((void**)&attn,    g_attn);
    cudaGetSymbolAddress((void**)&attnout, g_attnout);
    cudaGetSymbolAddress((void**)&hbuf,    g_hbuf);
    cudaGetSymbolAddress((void**)&gate,    g_gate);
    cudaGetSymbolAddress((void**)&up,      g_up);
    cudaGetSymbolAddress((void**)&ffn,     g_ffn);

    // --- low-rank down-projections (N=64 -> keep fp32 sgemm) ---
    sgemm_nn<<<dim3(1, 128, 1), 256>>>(x,  W_dq,  cq,  T_, RQ_,  D_, D_, RQ_,  RQ_, 0, 0, 0);
    sgemm_nn<<<dim3(1, 128, 1), 256>>>(x,  W_dkv, ckv, T_, RKV_, D_, D_, RKV_, RKV_, 0, 0, 0);

    // --- up-projections on tensor cores (K=64) ---
    tgemm3x<<<dim3(16, 128, 1), 256>>>(cq,  W_uq, q, T_, H_ * DH_,  RQ_,
                                       RQ_,  H_ * DH_,  H_ * DH_, 0, 0, 0);
    tgemm3x<<<dim3(8, 128, 1), 256>>>(ckv, W_uk, k, T_, HKV_ * DH_, RKV_,
                                      RKV_, HKV_ * DH_, HKV_ * DH_, 0, 0, 0);
    tgemm3x<<<dim3(8, 128, 1), 256>>>(ckv, W_uv, v, T_, HKV_ * DH_, RKV_,
                                      RKV_, HKV_ * DH_, HKV_ * DH_, 0, 0, 0);

    // --- random Fourier features ---
    phi_kernel<<<B_ * H_   * S_, 64>>>(q, omega, phiq, H_,   H_   * DH_);
    phi_kernel<<<B_ * HKV_ * S_, 64>>>(k, omega, phik, HKV_, HKV_ * DH_);

    // --- linear attention state ---
    z_kernel<<<B_ * HKV_, 128>>>(phik, z);
    kv_partial<<<B_ * HKV_ * NSPLIT, 256>>>(phik, v, kvpart);
    kv_reduce_expand<<<(B_ * H_ * F_ * DH_ + 255) / 256, 256>>>(kvpart, kvx);
    den_kernel<<<(B_ * H_ * S_) / 8, 256>>>(phiq, z, den);

    // num = phi_q @ kv (batched over B*H) on tensor cores
    tgemm3x<<<dim3(1, 32, B_ * H_), 256>>>(phiq, kvx, num,
                                           S_, DH_, F_, F_, DH_, DH_,
                                           (long long)S_ * F_,
                                           (long long)F_ * DH_,
                                           (long long)S_ * DH_);
    attn_assemble<<<(B_ * H_ * S_ * DH_ + 255) / 256, 256>>>(num, den, attn);

    // --- output projection + residual/LN ---
    tgemm3x<<<dim3(16, 128, 1), 256>>>(attn, W_o, attnout, T_, D_, D_,
                                       D_, D_, D_, 0, 0, 0);
    add_ln_kernel<<<T_, 256>>>(x, attnout, ln1_g, ln1_b, hbuf);

    // --- SwiGLU FFN on tensor cores ---
    tgemm3x<<<dim3(64, 128, 1), 256>>>(hbuf, gate_W, gate, T_, DFF_, D_,
                                       D_, DFF_, DFF_, 0, 0, 0);
    tgemm3x<<<dim3(64, 128, 1), 256>>>(hbuf, up_W,   up,   T_, DFF_, D_,
                                       D_, DFF_, DFF_, 0, 0, 0);
    swiglu_kernel<<<(int)(((long long)T_ * DFF_ + 255) / 256), 256>>>(gate, up);
    tgemm3x<<<dim3(16, 128, 1), 256>>>(gate, down_W, ffn, T_, D_, DFF_,
                                       DFF_, D_, D_, 0, 0, 0);

    // --- final residual/LN -> output ---
    add_ln_kernel<<<T_, 256>>>(hbuf, ffn, ln2_g, ln2_b, out);
}

// round 13
// speedup vs baseline: 1.0028x; 1.0020x over previous
#include <cuda_runtime.h>
#include <math.h>

// ---------------------------------------------------------------------------
// MLGKA layer. R5: big GEMMs on tensor cores via mma.sync m16n8k8 tf32 with
// 3xTF32 error compensation (hi/lo split) -> fp32-grade accuracy at tensor
// speed. Attention plumbing / LN / swiglu unchanged from the passing R4.
// ---------------------------------------------------------------------------

constexpr int B_    = 4;
constexpr int S_    = 4096;
constexpr int T_    = B_ * S_;        // 16384 tokens
constexpr int D_    = 2048;
constexpr int DFF_  = 8192;
constexpr int H_    = 16;
constexpr int HKV_  = 8;
constexpr int DH_   = 128;
constexpr int RQ_   = 64;
constexpr int RKV_  = 64;
constexpr int KD_   = 64;
constexpr int F_    = 128;            // 2*KD
constexpr int NSPLIT = 8;
constexpr int CHUNK  = S_ / NSPLIT;   // 512

// ------------------------------ scratch (static device globals) -----------
__device__ float g_cq     [(size_t)T_ * RQ_];
__device__ float g_ckv    [(size_t)T_ * RKV_];
__device__ float g_q      [(size_t)T_ * (H_  * DH_)];
__device__ float g_k      [(size_t)T_ * (HKV_* DH_)];
__device__ float g_v      [(size_t)T_ * (HKV_* DH_)];
__device__ float g_phiq   [(size_t)B_ * H_   * S_ * F_];
__device__ float g_phik   [(size_t)B_ * HKV_ * S_ * F_];
__device__ float g_kvpart [(size_t)B_ * HKV_ * NSPLIT * F_ * DH_];
__device__ float g_kvx    [(size_t)B_ * H_   * F_ * DH_];
__device__ float g_z      [(size_t)B_ * HKV_ * F_];
__device__ float g_den    [(size_t)B_ * H_   * S_];
__device__ float g_num    [(size_t)B_ * H_   * S_ * DH_];
__device__ float g_attn   [(size_t)T_ * D_];
__device__ float g_attnout[(size_t)T_ * D_];
__device__ float g_hbuf   [(size_t)T_ * D_];
__device__ float g_gate   [(size_t)T_ * DFF_];
__device__ float g_up     [(size_t)T_ * DFF_];
__device__ float g_ffn    [(size_t)T_ * D_];

// =========================== tensor-core GEMM (3xTF32) =====================
// C[M,N] = A[M,K] @ B[K,N], row-major, fp32 in/out, fp32-grade accuracy via
// hi/lo tf32 split. Requirements: M%128==0, N%128==0, K%8==0,
// C 8B-aligned rows (ldc even). Batched via blockIdx.z strides.

__device__ __forceinline__ float f2tf32(float x) {
    unsigned u;
    asm("cvt.rna.tf32.f32 %0, %1;" : "=r"(u) : "f"(x));
    return __uint_as_float(u);
}

__device__ __forceinline__ void mma8(float4& d, const float* a, const float* b) {
    asm("mma.sync.aligned.m16n8k8.row.col.f32.tf32.tf32.f32 "
        "{%0,%1,%2,%3}, {%4,%5,%6,%7}, {%8,%9}, {%0,%1,%2,%3};"
        : "+f"(d.x), "+f"(d.y), "+f"(d.z), "+f"(d.w)
        : "r"(__float_as_uint(a[0])), "r"(__float_as_uint(a[1])),
          "r"(__float_as_uint(a[2])), "r"(__float_as_uint(a[3])),
          "r"(__float_as_uint(b[0])), "r"(__float_as_uint(b[1])));
}

// smem tile: [k(8)][m or n (128) + pad 8] -> pitch 136 floats.
// Fragment LDS bank = (136*k + idx) % 32 = (8*k + idx%32): tig in 0..3,
// g in 0..7 -> 8*tig+g unique in 0..31 => conflict-free.
__device__ __forceinline__ void compute_step(
    const float (*sAh)[136], const float (*sAl)[136],
    const float (*sBh)[136], const float (*sBl)[136],
    int m0, int n0, int g, int tig, float4 acc[4][4])
{
    float ah[4][4], al[4][4];
#pragma unroll
    for (int im = 0; im < 4; im++) {
        const int r = m0 + im * 16 + g;
        ah[im][0] = sAh[tig    ][r];     ah[im][1] = sAh[tig    ][r + 8];
        ah[im][2] = sAh[tig + 4][r];     ah[im][3] = sAh[tig + 4][r + 8];
        al[im][0] = sAl[tig    ][r];     al[im][1] = sAl[tig    ][r + 8];
        al[im][2] = sAl[tig + 4][r];     al[im][3] = sAl[tig + 4][r + 8];
    }
    float bh[4][2], bl[4][2];
#pragma unroll
    for (int in_ = 0; in_ < 4; in_++) {
        const int nb = n0 + in_ * 8 + g;
        bh[in_][0] = sBh[tig][nb];       bh[in_][1] = sBh[tig + 4][nb];
        bl[in_][0] = sBl[tig][nb];       bl[in_][1] = sBl[tig + 4][nb];
    }
#pragma unroll
    for (int im = 0; im < 4; im++)
#pragma unroll
        for (int in_ = 0; in_ < 4; in_++) {
            mma8(acc[im][in_], ah[im], bh[in_]);   // hi*hi
            mma8(acc[im][in_], ah[im], bl[in_]);   // hi*lo
            mma8(acc[im][in_], al[im], bh[in_]);   // lo*hi
        }
}

__global__ __launch_bounds__(256)
void tgemm3x(const float* __restrict__ A, const float* __restrict__ Bm,
             float* __restrict__ C, int M, int N, int K,
             int lda, int ldb, int ldc,
             long long sA, long long sB, long long sC)
{
    A  += (long long)blockIdx.z * sA;
    Bm += (long long)blockIdx.z * sB;
    C  += (long long)blockIdx.z * sC;

    __shared__ __align__(16) float sAh[2][8][136], sAl[2][8][136];
    __shared__ __align__(16) float sBh[2][8][136], sBl[2][8][136];

    const int tid  = threadIdx.x;
    const int w    = tid >> 5;
    const int lane = tid & 31;
    const int g    = lane >> 2;
    const int tig  = lane & 3;
    const int m0   = (w & 1) * 64;      // warp grid 2 (M) x 4 (N)
    const int n0   = (w >> 1) * 32;
    const int rowBase = blockIdx.y * 128;
    const int colBase = blockIdx.x * 128;

    // loaders: A tile 128x8 (one float4/thread along k), B tile 8x128
    const int aRow = tid >> 1, aK = (tid & 1) << 2;
    const int bK   = tid >> 5, bN = (tid & 31) << 2;
    const float* Ap = A + (size_t)(rowBase + aRow) * lda + aK;
    const float* Bp = Bm + (size_t)bK * ldb + colBase + bN;

    float4 acc[4][4];
#pragma unroll
    for (int i = 0; i < 4; i++)
#pragma unroll
        for (int j = 0; j < 4; j++) acc[i][j] = make_float4(0.f, 0.f, 0.f, 0.f);

    // ---- fill buffer 0 ----
    float4 a4 = *reinterpret_cast<const float4*>(Ap);
    float4 b4 = *reinterpret_cast<const float4*>(Bp);
    {
        float av[4] = {a4.x, a4.y, a4.z, a4.w};
#pragma unroll
        for (int j = 0; j < 4; j++) {
            float hi = f2tf32(av[j]);
            sAh[0][aK + j][aRow] = hi;
            sAl[0][aK + j][aRow] = f2tf32(av[j] - hi);
        }
        float4 bhv, blv;
        bhv.x = f2tf32(b4.x); blv.x = f2tf32(b4.x - bhv.x);
        bhv.y = f2tf32(b4.y); blv.y = f2tf32(b4.y - bhv.y);
        bhv.z = f2tf32(b4.z); blv.z = f2tf32(b4.z - bhv.z);
        bhv.w = f2tf32(b4.w); blv.w = f2tf32(b4.w - bhv.w);
        *reinterpret_cast<float4*>(&sBh[0][bK][bN]) = bhv;
        *reinterpret_cast<float4*>(&sBl[0][bK][bN]) = blv;
    }
    __syncthreads();

    int buf = 0;
    for (int k0 = 8; k0 < K; k0 += 8) {
        // prefetch next tile
        a4 = *reinterpret_cast<const float4*>(Ap + k0);
        b4 = *reinterpret_cast<const float4*>(Bp + (size_t)k0 * ldb);

        compute_step(sAh[buf], sAl[buf], sBh[buf], sBl[buf], m0, n0, g, tig, acc);

        const int nb = buf ^ 1;
        float av[4] = {a4.x, a4.y, a4.z, a4.w};
#pragma unroll
        for (int j = 0; j < 4; j++) {
            float hi = f2tf32(av[j]);
            sAh[nb][aK + j][aRow] = hi;
            sAl[nb][aK + j][aRow] = f2tf32(av[j] - hi);
        }
        float4 bhv, blv;
        bhv.x = f2tf32(b4.x); blv.x = f2tf32(b4.x - bhv.x);
        bhv.y = f2tf32(b4.y); blv.y = f2tf32(b4.y - bhv.y);
        bhv.z = f2tf32(b4.z); blv.z = f2tf32(b4.z - bhv.z);
        bhv.w = f2tf32(b4.w); blv.w = f2tf32(b4.w - bhv.w);
        *reinterpret_cast<float4*>(&sBh[nb][bK][bN]) = bhv;
        *reinterpret_cast<float4*>(&sBl[nb][bK][bN]) = blv;
        __syncthreads();
        buf = nb;
    }
    compute_step(sAh[buf], sAl[buf], sBh[buf], sBl[buf], m0, n0, g, tig, acc);

    // ---- epilogue (no guards: M,N multiples of 128) ----
#pragma unroll
    for (int im = 0; im < 4; im++) {
        const int r = rowBase + m0 + im * 16 + g;
#pragma unroll
        for (int in_ = 0; in_ < 4; in_++) {
            const int cc = colBase + n0 + in_ * 8 + 2 * tig;
            float2 v0 = make_float2(acc[im][in_].x, acc[im][in_].y);
            float2 v1 = make_float2(acc[im][in_].z, acc[im][in_].w);
            *reinterpret_cast<float2*>(C + (size_t)r * ldc + cc)       = v0;
            *reinterpret_cast<float2*>(C + (size_t)(r + 8) * ldc + cc) = v1;
        }
    }
}

// ------------------------------ fp32 SGEMM (small N / ragged shapes) ------
__global__ __launch_bounds__(256, 2)
void sgemm_nn(const float* __restrict__ A, const float* __restrict__ Bm,
              float* __restrict__ C,
              int M, int N, int K, int lda, int ldb, int ldc,
              long long sA, long long sB, long long sC)
{
    A  += (long long)blockIdx.z * sA;
    Bm += (long long)blockIdx.z * sB;
    C  += (long long)blockIdx.z * sC;

    __shared__ float As[8][132];
    __shared__ float Bs[8][128];

    const int tid = threadIdx.x;
    const int tx  = tid & 15;
    const int ty  = tid >> 4;
    const int rowBase = blockIdx.y * 128;
    const int colBase = blockIdx.x * 128;

    const int aRow = tid >> 1;
    const int aCol = (tid & 1) << 2;
    const int bRow = tid >> 5;
    const int bCol = (tid & 31) << 2;

    float acc[8][8];
#pragma unroll
    for (int i = 0; i < 8; i++)
#pragma unroll
        for (int j = 0; j < 8; j++) acc[i][j] = 0.f;

    const int  gArow = rowBase + aRow;
    const bool aInM  = (gArow < M);
    const float* Aptr = A + (size_t)(aInM ? gArow : 0) * lda + aCol;
    const int  gBcol = colBase + bCol;

    for (int k0 = 0; k0 < K; k0 += 8) {
        float4 a4 = make_float4(0.f, 0.f, 0.f, 0.f);
        if (aInM) a4 = *reinterpret_cast<const float4*>(Aptr + k0);
        As[aCol + 0][aRow] = a4.x;
        As[aCol + 1][aRow] = a4.y;
        As[aCol + 2][aRow] = a4.z;
        As[aCol + 3][aRow] = a4.w;

        float4 b4;
        const float* bp = Bm + (size_t)(k0 + bRow) * ldb;
        if (gBcol + 3 < N) {
            b4 = *reinterpret_cast<const float4*>(bp + gBcol);
        } else {
            b4.x = (gBcol + 0 < N) ? bp[gBcol + 0] : 0.f;
            b4.y = (gBcol + 1 < N) ? bp[gBcol + 1] : 0.f;
            b4.z = (gBcol + 2 < N) ? bp[gBcol + 2] : 0.f;
            b4.w = (gBcol + 3 < N) ? bp[gBcol + 3] : 0.f;
        }
        *reinterpret_cast<float4*>(&Bs[bRow][bCol]) = b4;
        __syncthreads();

#pragma unroll
        for (int kk = 0; kk < 8; kk++) {
            float aR[8], bR[8];
#pragma unroll
            for (int i = 0; i < 8; i++) aR[i] = As[kk][ty + 16 * i];
#pragma unroll
            for (int j = 0; j < 8; j++) bR[j] = Bs[kk][tx + 16 * j];
#pragma unroll
            for (int i = 0; i < 8; i++)
#pragma unroll
                for (int j = 0; j < 8; j++) acc[i][j] += aR[i] * bR[j];
        }
        __syncthreads();
    }

#pragma unroll
    for (int i = 0; i < 8; i++) {
        int r = rowBase + ty + 16 * i;
        if (r >= M) continue;
        float* crow = C + (size_t)r * ldc;
#pragma unroll
        for (int j = 0; j < 8; j++) {
            int c = colBase + tx + 16 * j;
            if (c < N) crow[c] = acc[i][j];
        }
    }
}

// ------------------------------ phi (random Fourier features) -------------
__global__ void phi_kernel(const float* __restrict__ qk,
                           const float* __restrict__ omega,
                           float* __restrict__ phi,
                           int nheads, int ldq)
{
    const long long bid = blockIdx.x;             // ((b*nh + h)*S + s)
    const int s = (int)(bid % S_);
    const int h = (int)((bid / S_) % nheads);
    const int b = (int)(bid / ((long long)S_ * nheads));
    const long long t = (long long)b * S_ + s;

    __shared__ float qs[DH_];
    const int k = threadIdx.x;                    // 0..63
    const float* row = qk + (size_t)t * ldq + (size_t)h * DH_;
    qs[k]      = row[k];
    qs[k + 64] = row[k + 64];
    __syncthreads();

    float proj = 0.f;
#pragma unroll 8
    for (int d = 0; d < DH_; d++) proj += qs[d] * omega[d * KD_ + k];

    float sv, cv;
    sincosf(proj, &sv, &cv);
    float* prow = phi + bid * (long long)F_;
    prow[k]      = cv * 0.125f;     // 1/sqrt(64)
    prow[k + 64] = sv * 0.125f;
}

// ------------------------------ z = sum_s phi_k ---------------------------
__global__ void z_kernel(const float* __restrict__ phik, float* __restrict__ z)
{
    const int bh = blockIdx.x;
    const int f  = threadIdx.x;
    const float* p = phik + (size_t)bh * S_ * F_ + f;
    float sum = 0.f;
#pragma unroll 8
    for (int i = 0; i < S_; i++) sum += p[(size_t)i * F_];
    z[bh * F_ + f] = sum;
}

// ------------------------------ kv partial --------------------------------
__global__ __launch_bounds__(256, 2)
void kv_partial(const float* __restrict__ phik, const float* __restrict__ v,
                float* __restrict__ part)
{
    const int bid   = blockIdx.x;
    const int split = bid % NSPLIT;
    const int bh    = bid / NSPLIT;
    const int b     = bh / HKV_;
    const int hk    = bh % HKV_;

    const float* A  = phik + (size_t)bh * S_ * F_ + (size_t)split * CHUNK * F_;
    const float* Bm = v + ((size_t)b * S_ + (size_t)split * CHUNK) * (HKV_ * DH_)
                        + (size_t)hk * DH_;
    float* C = part + (size_t)bid * F_ * DH_;

    __shared__ float As[8][128];
    __shared__ float Bs[8][128];
    const int tid = threadIdx.x;
    const int tx  = tid & 15;
    const int ty  = tid >> 4;
    const int lRow = tid >> 5;
    const int lCol = (tid & 31) << 2;

    float acc[8][8];
#pragma unroll
    for (int i = 0; i < 8; i++)
#pragma unroll
        for (int j = 0; j < 8; j++) acc[i][j] = 0.f;

    for (int k0 = 0; k0 < CHUNK; k0 += 8) {
        *reinterpret_cast<float4*>(&As[lRow][lCol]) =
            *reinterpret_cast<const float4*>(A + (size_t)(k0 + lRow) * F_ + lCol);
        *reinterpret_cast<float4*>(&Bs[lRow][lCol]) =
            *reinterpret_cast<const float4*>(Bm + (size_t)(k0 + lRow) * (HKV_ * DH_) + lCol);
        __syncthreads();
#pragma unroll
        for (int kk = 0; kk < 8; kk++) {
            float aR[8], bR[8];
#pragma unroll
            for (int i = 0; i < 8; i++) aR[i] = As[kk][ty + 16 * i];
#pragma unroll
            for (int j = 0; j < 8; j++) bR[j] = Bs[kk][tx + 16 * j];
#pragma unroll
            for (int i = 0; i < 8; i++)
#pragma unroll
                for (int j = 0; j < 8; j++) acc[i][j] += aR[i] * bR[j];
        }
        __syncthreads();
    }
#pragma unroll
    for (int i = 0; i < 8; i++)
#pragma unroll
        for (int j = 0; j < 8; j++)
            C[(size_t)(ty + 16 * i) * DH_ + (tx + 16 * j)] = acc[i][j];
}

// ------------------------------ reduce splits + GQA expand ----------------
__global__ void kv_reduce_expand(const float* __restrict__ part,
                                 float* __restrict__ kvx)
{
    const long long n = (long long)B_ * H_ * F_ * DH_;
    long long i = (long long)blockIdx.x * blockDim.x + threadIdx.x;
    if (i >= n) return;
    const int fd = (int)(i & (F_ * DH_ - 1));
    const int h  = (int)((i >> 14) & (H_ - 1));
    const int b  = (int)(i >> 18);
    const int bh = b * HKV_ + (h >> 1);
    float s = 0.f;
#pragma unroll
    for (int sp = 0; sp < NSPLIT; sp++)
        s += part[(((size_t)bh * NSPLIT + sp) << 14) + fd];
    kvx[i] = s;
}

// ------------------------------ den ---------------------------------------
__global__ void den_kernel(const float* __restrict__ phiq,
                           const float* __restrict__ z,
                           float* __restrict__ den)
{
    const long long warp = ((long long)blockIdx.x * blockDim.x + threadIdx.x) >> 5;
    const int lane = threadIdx.x & 31;
    if (warp >= (long long)B_ * H_ * S_) return;
    const int h = (int)((warp / S_) % H_);
    const int b = (int)(warp / ((long long)S_ * H_));
    const float* zp = z + (size_t)(b * HKV_ + (h >> 1)) * F_;
    const float* pr = phiq + warp * (long long)F_;
    float sum = 0.f;
#pragma unroll
    for (int j = 0; j < 4; j++) {
        int f = lane + 32 * j;
        sum += pr[f] * zp[f];
    }
#pragma unroll
    for (int o = 16; o; o >>= 1) sum += __shfl_xor_sync(0xffffffffu, sum, o);
    if (lane == 0) den[warp] = sum;
}

// ------------------------------ attn assembly -----------------------------
__global__ void attn_assemble(const float* __restrict__ num,
                              const float* __restrict__ den,
                              float* __restrict__ attn)
{
    const long long n = (long long)B_ * H_ * S_ * DH_;
    long long i = (long long)blockIdx.x * blockDim.x + threadIdx.x;
    if (i >= n) return;
    const int d = (int)(i & (DH_ - 1));
    const long long r = i >> 7;
    const int s = (int)(r & (S_ - 1));
    const int h = (int)((r >> 12) & (H_ - 1));
    const int b = (int)(r >> 16);
    const float val = num[i] / (den[r] + 1e-6f);
    attn[((size_t)b * S_ + s) * (size_t)D_ + (size_t)h * DH_ + d] = val;
}

// ------------------------------ out = LN(a+b)*g + beta --------------------
__global__ __launch_bounds__(256)
void add_ln_kernel(const float* __restrict__ a, const float* __restrict__ bb,
                   const float* __restrict__ g, const float* __restrict__ beta,
                   float* __restrict__ out)
{
    __shared__ float sh[10];
    const size_t row = blockIdx.x;
    const float* ar = a  + row * D_;
    const float* br = bb + row * D_;
    const int tid = threadIdx.x;

    float loc[8];
    float sum = 0.f;
#pragma unroll
    for (int j = 0; j < 8; j++) {
        int c = tid + 256 * j;
        float v = ar[c] + br[c];
        loc[j] = v;
        sum += v;
    }
#pragma unroll
    for (int o = 16; o; o >>= 1) sum += __shfl_xor_sync(0xffffffffu, sum, o);
    if ((tid & 31) == 0) sh[tid >> 5] = sum;
    __syncthreads();
    if (tid == 0) {
        float s = 0.f;
        for (int i = 0; i < 8; i++) s += sh[i];
        sh[8] = s;
    }
    __syncthreads();
    const float mu = sh[8] * (1.f / D_);

    float sq = 0.f;
#pragma unroll
    for (int j = 0; j < 8; j++) {
        float dv = loc[j] - mu;
        sq += dv * dv;
    }
    __syncthreads();
#pragma unroll
    for (int o = 16; o; o >>= 1) sq += __shfl_xor_sync(0xffffffffu, sq, o);
    if ((tid & 31) == 0) sh[tid >> 5] = sq;
    __syncthreads();
    if (tid == 0) {
        float s = 0.f;
        for (int i = 0; i < 8; i++) s += sh[i];
        sh[9] = s;
    }
    __syncthreads();
    const float rstd = rsqrtf(sh[9] * (1.f / D_) + 1e-5f);

    float* orow = out + row * D_;
#pragma unroll
    for (int j = 0; j < 8; j++) {
        int c = tid + 256 * j;
        orow[c] = (loc[j] - mu) * rstd * g[c] + beta[c];
    }
}

// ------------------------------ gate *= silu(up) --------------------------
__global__ void swiglu_kernel(float* __restrict__ gate,
                              const float* __restrict__ up)
{
    const long long n = (long long)T_ * DFF_;
    long long i = (long long)blockIdx.x * blockDim.x + threadIdx.x;
    if (i >= n) return;
    const float u = up[i];
    const float s = u / (1.f + expf(-u));
    gate[i] = gate[i] * s;
}

// ---------------------------------------------------------------------------
extern "C" void kernel_launch(void* const* d_in, const int* in_sizes, int n_in,
                              void* d_out, int out_size)
{
    const float* x      = (const float*)d_in[0];
    const float* W_dq   = (const float*)d_in[1];
    const float* W_uq   = (const float*)d_in[2];
    const float* W_dkv  = (const float*)d_in[3];
    const float* W_uk   = (const float*)d_in[4];
    const float* W_uv   = (const float*)d_in[5];
    const float* omega  = (const float*)d_in[6];
    const float* W_o    = (const float*)d_in[7];
    const float* ln1_g  = (const float*)d_in[8];
    const float* ln1_b  = (const float*)d_in[9];
    const float* gate_W = (const float*)d_in[10];
    const float* up_W   = (const float*)d_in[11];
    const float* down_W = (const float*)d_in[12];
    const float* ln2_g  = (const float*)d_in[13];
    const float* ln2_b  = (const float*)d_in[14];
    float* out = (float*)d_out;

    float *cq, *ckv, *q, *k, *v, *phiq, *phik, *kvpart, *kvx, *z, *den, *num;
    float *attn, *attnout, *hbuf, *gate, *up, *ffn;
    cudaGetSymbolAddress((void**)&cq,      g_cq);
    cudaGetSymbolAddress((void**)&ckv,     g_ckv);
    cudaGetSymbolAddress((void**)&q,       g_q);
    cudaGetSymbolAddress((void**)&k,       g_k);
    cudaGetSymbolAddress((void**)&v,       g_v);
    cudaGetSymbolAddress((void**)&phiq,    g_phiq);
    cudaGetSymbolAddress((void**)&phik,    g_phik);
    cudaGetSymbolAddress((void**)&kvpart,  g_kvpart);
    cudaGetSymbolAddress((void**)&kvx,     g_kvx);
    cudaGetSymbolAddress((void**)&z,       g_z);
    cudaGetSymbolAddress((void**)&den,     g_den);
    cudaGetSymbolAddress((void**)&num,     g_num);
    cudaGetSymbolAddress((void**)&attn,    g_attn);
    cudaGetSymbolAddress((void**)&attnout, g_attnout);
    cudaGetSymbolAddress((void**)&hbuf,    g_hbuf);
    cudaGetSymbolAddress((void**)&gate,    g_gate);
    cudaGetSymbolAddress((void**)&up,      g_up);
    cudaGetSymbolAddress((void**)&ffn,     g_ffn);

    // --- low-rank down-projections (N=64 -> keep fp32 sgemm) ---
    sgemm_nn<<<dim3(1, 128, 1), 256>>>(x,  W_dq,  cq,  T_, RQ_,  D_, D_, RQ_,  RQ_, 0, 0, 0);
    sgemm_nn<<<dim3(1, 128, 1), 256>>>(x,  W_dkv, ckv, T_, RKV_, D_, D_, RKV_, RKV_, 0, 0, 0);

    // --- up-projections on tensor cores (K=64) ---
    tgemm3x<<<dim3(16, 128, 1), 256>>>(cq,  W_uq, q, T_, H_ * DH_,  RQ_,
                                       RQ_,  H_ * DH_,  H_ * DH_, 0, 0, 0);
    tgemm3x<<<dim3(8, 128, 1), 256>>>(ckv, W_uk, k, T_, HKV_ * DH_, RKV_,
                                      RKV_, HKV_ * DH_, HKV_ * DH_, 0, 0, 0);
    tgemm3x<<<dim3(8, 128, 1), 256>>>(ckv, W_uv, v, T_, HKV_ * DH_, RKV_,
                                      RKV_, HKV_ * DH_, HKV_ * DH_, 0, 0, 0);

    // --- random Fourier features ---
    phi_kernel<<<B_ * H_   * S_, 64>>>(q, omega, phiq, H_,   H_   * DH_);
    phi_kernel<<<B_ * HKV_ * S_, 64>>>(k, omega, phik, HKV_, HKV_ * DH_);

    // --- linear attention state ---
    z_kernel<<<B_ * HKV_, 128>>>(phik, z);
    kv_partial<<<B_ * HKV_ * NSPLIT, 256>>>(phik, v, kvpart);
    kv_reduce_expand<<<(B_ * H_ * F_ * DH_ + 255) / 256, 256>>>(kvpart, kvx);
    den_kernel<<<(B_ * H_ * S_) / 8, 256>>>(phiq, z, den);

    // num = phi_q @ kv (batched over B*H) on tensor cores
    tgemm3x<<<dim3(1, 32, B_ * H_), 256>>>(phiq, kvx, num,
                                           S_, DH_, F_, F_, DH_, DH_,
                                           (long long)S_ * F_,
                                           (long long)F_ * DH_,
                                           (long long)S_ * DH_);
    attn_assemble<<<(B_ * H_ * S_ * DH_ + 255) / 256, 256>>>(num, den, attn);

    // --- output projection + residual/LN ---
    tgemm3x<<<dim3(16, 128, 1), 256>>>(attn, W_o, attnout, T_, D_, D_,
                                       D_, D_, D_, 0, 0, 0);
    add_ln_kernel<<<T_, 256>>>(x, attnout, ln1_g, ln1_b, hbuf);

    // --- SwiGLU FFN on tensor cores ---
    tgemm3x<<<dim3(64, 128, 1), 256>>>(hbuf, gate_W, gate, T_, DFF_, D_,
                                       D_, DFF_, DFF_, 0, 0, 0);
    tgemm3x<<<dim3(64, 128, 1), 256>>>(hbuf, up_W,   up,   T_, DFF_, D_,
                                       D_, DFF_, DFF_, 0, 0, 0);
    swiglu_kernel<<<(int)(((long long)T_ * DFF_ + 255) / 256), 256>>>(gate, up);
    tgemm3x<<<dim3(16, 128, 1), 256>>>(gate, down_W, ffn, T_, D_, DFF_,
                                       DFF_, D_, D_, 0, 0, 0);

    // --- final residual/LN -> output ---
    add_ln_kernel<<<T_, 256>>>(hbuf, ffn, ln2_g, ln2_b, out);
}